// round 1
// baseline (speedup 1.0000x reference)
#include <cuda_runtime.h>
#include <math.h>

#define BB  8
#define TT  4096
#define CC  1024
#define HSX 64
#define NKP 2048           // ceil(T/2) gathered queries
#define QSCALE 0.03125f    // C^-0.5 = 1/32

// ---------------- scratch (device globals; no allocations allowed) ----------
__device__ int   g_keep[NKP];
__device__ float g_K[(size_t)BB * TT * HSX];    // 8 MB
__device__ float g_V[(size_t)BB * TT * HSX];    // 8 MB
__device__ float g_Q[(size_t)BB * NKP * HSX];   // 4 MB (pre-scaled by 1/32)

// ---------------- keep indices (exact match of the Python formula) ----------
__global__ void keep_kernel() {
    int i = blockIdx.x * blockDim.x + threadIdx.x;
    if (i >= NKP) return;
    const int a = (TT + 3) / 4;          // 1024
    int x = NKP - 1 - i;                 // list is reversed
    int v;
    if (x < a) {
        v = TT - 1 - x;
    } else {
        int k = x - a;
        // 3/1024 * k^2 + 1024 is exact in double -> ceil matches math.ceil
        double t = (3.0 / (double)a) * (double)k * (double)k + (double)a;
        v = TT - 1 - (int)ceil(t);
    }
    g_keep[i] = v;
}

// ---------------- K,V projection: X[32768,1024] @ Wkv^T[1024,128] ------------
__global__ __launch_bounds__(256) void proj_kv_kernel(
    const float* __restrict__ x,
    const float* __restrict__ Wk, const float* __restrict__ bk,
    const float* __restrict__ Wv, const float* __restrict__ bv)
{
    __shared__ float As[16][64];    // [kk][m]
    __shared__ float Bs[16][128];   // [kk][n]
    const int tid = threadIdx.x;
    const int ty = tid >> 4, tx = tid & 15;
    const size_t m0 = (size_t)blockIdx.x * 64;

    float acc[4][8];
#pragma unroll
    for (int i = 0; i < 4; i++)
#pragma unroll
        for (int j = 0; j < 8; j++) acc[i][j] = 0.f;

    const int ar = tid >> 2;          // 0..63
    const int ac = (tid & 3) * 4;     // 0,4,8,12

    for (int k0 = 0; k0 < CC; k0 += 16) {
        // prefetch to regs before the barrier
        float4 av = *(const float4*)(x + (m0 + ar) * CC + k0 + ac);
        float4 bvv[2];
#pragma unroll
        for (int s = 0; s < 2; s++) {
            int idx = tid + s * 256;
            int n   = idx >> 2;            // 0..127
            int c   = (idx & 3) * 4;
            const float* W = (n < 64) ? (Wk + (size_t)n * CC)
                                      : (Wv + (size_t)(n - 64) * CC);
            bvv[s] = *(const float4*)(W + k0 + c);
        }
        __syncthreads();                   // previous tile fully consumed
        As[ac + 0][ar] = av.x; As[ac + 1][ar] = av.y;
        As[ac + 2][ar] = av.z; As[ac + 3][ar] = av.w;
#pragma unroll
        for (int s = 0; s < 2; s++) {
            int idx = tid + s * 256;
            int n   = idx >> 2;
            int c   = (idx & 3) * 4;
            Bs[c + 0][n] = bvv[s].x; Bs[c + 1][n] = bvv[s].y;
            Bs[c + 2][n] = bvv[s].z; Bs[c + 3][n] = bvv[s].w;
        }
        __syncthreads();
#pragma unroll
        for (int kk = 0; kk < 16; kk++) {
            float4 a4 = *(const float4*)&As[kk][4 * ty];
            float4 b0 = *(const float4*)&Bs[kk][8 * tx];
            float4 b1 = *(const float4*)&Bs[kk][8 * tx + 4];
            float a_[4] = {a4.x, a4.y, a4.z, a4.w};
            float b_[8] = {b0.x, b0.y, b0.z, b0.w, b1.x, b1.y, b1.z, b1.w};
#pragma unroll
            for (int i = 0; i < 4; i++)
#pragma unroll
                for (int j = 0; j < 8; j++) acc[i][j] += a_[i] * b_[j];
        }
    }

    const int n0 = 8 * tx;
    if (n0 < 64) {
        float4 bl = *(const float4*)(bk + n0);
        float4 bh = *(const float4*)(bk + n0 + 4);
#pragma unroll
        for (int i = 0; i < 4; i++) {
            size_t row = m0 + 4 * ty + i;
            float4 r0 = make_float4(acc[i][0] + bl.x, acc[i][1] + bl.y,
                                    acc[i][2] + bl.z, acc[i][3] + bl.w);
            float4 r1 = make_float4(acc[i][4] + bh.x, acc[i][5] + bh.y,
                                    acc[i][6] + bh.z, acc[i][7] + bh.w);
            *(float4*)(g_K + row * HSX + n0)     = r0;
            *(float4*)(g_K + row * HSX + n0 + 4) = r1;
        }
    } else {
        int nv = n0 - 64;
        float4 bl = *(const float4*)(bv + nv);
        float4 bh = *(const float4*)(bv + nv + 4);
#pragma unroll
        for (int i = 0; i < 4; i++) {
            size_t row = m0 + 4 * ty + i;
            float4 r0 = make_float4(acc[i][0] + bl.x, acc[i][1] + bl.y,
                                    acc[i][2] + bl.z, acc[i][3] + bl.w);
            float4 r1 = make_float4(acc[i][4] + bh.x, acc[i][5] + bh.y,
                                    acc[i][6] + bh.z, acc[i][7] + bh.w);
            *(float4*)(g_V + row * HSX + nv)     = r0;
            *(float4*)(g_V + row * HSX + nv + 4) = r1;
        }
    }
}

// ---------------- gathered Q projection (scaled by 1/32) --------------------
__global__ __launch_bounds__(256) void proj_q_kernel(
    const float* __restrict__ x,
    const float* __restrict__ Wq, const float* __restrict__ bq)
{
    __shared__ float As[16][64];
    __shared__ float Bs[16][64];
    __shared__ int   rows[64];
    const int tid = threadIdx.x;
    const int ty = tid >> 4, tx = tid & 15;
    const size_t m0 = (size_t)blockIdx.x * 64;
    const int b  = (int)(m0 / NKP);
    const int q0 = (int)(m0 % NKP);

    if (tid < 64) rows[tid] = g_keep[q0 + tid];
    __syncthreads();

    float acc[4][4];
#pragma unroll
    for (int i = 0; i < 4; i++)
#pragma unroll
        for (int j = 0; j < 4; j++) acc[i][j] = 0.f;

    const int ar = tid >> 2;
    const int ac = (tid & 3) * 4;
    const size_t xrow = (size_t)b * TT + rows[ar];

    for (int k0 = 0; k0 < CC; k0 += 16) {
        float4 av = *(const float4*)(x + xrow * CC + k0 + ac);
        float4 wv = *(const float4*)(Wq + (size_t)ar * CC + k0 + ac);
        __syncthreads();
        As[ac + 0][ar] = av.x; As[ac + 1][ar] = av.y;
        As[ac + 2][ar] = av.z; As[ac + 3][ar] = av.w;
        Bs[ac + 0][ar] = wv.x; Bs[ac + 1][ar] = wv.y;
        Bs[ac + 2][ar] = wv.z; Bs[ac + 3][ar] = wv.w;
        __syncthreads();
#pragma unroll
        for (int kk = 0; kk < 16; kk++) {
            float4 a4 = *(const float4*)&As[kk][4 * ty];
            float4 b4 = *(const float4*)&Bs[kk][4 * tx];
            float a_[4] = {a4.x, a4.y, a4.z, a4.w};
            float b_[4] = {b4.x, b4.y, b4.z, b4.w};
#pragma unroll
            for (int i = 0; i < 4; i++)
#pragma unroll
                for (int j = 0; j < 4; j++) acc[i][j] += a_[i] * b_[j];
        }
    }

    float4 bq4 = *(const float4*)(bq + 4 * tx);
    float bb[4] = {bq4.x, bq4.y, bq4.z, bq4.w};
#pragma unroll
    for (int i = 0; i < 4; i++) {
        size_t row = (size_t)b * NKP + q0 + 4 * ty + i;
        float4 r = make_float4((acc[i][0] + bb[0]) * QSCALE,
                               (acc[i][1] + bb[1]) * QSCALE,
                               (acc[i][2] + bb[2]) * QSCALE,
                               (acc[i][3] + bb[3]) * QSCALE);
        *(float4*)(g_Q + row * HSX + 4 * tx) = r;
    }
}

// ---------------- flash attention over gathered queries ---------------------
// Block: 64 queries x full masked key range, Bk=64 key tiles, online softmax.
__global__ __launch_bounds__(256) void attn_kernel(float* __restrict__ out) {
    extern __shared__ float sm[];
    float* Qs = sm;                  // [64][65]
    float* Ks = Qs + 64 * 65;        // [64][65]
    float* Vs = Ks + 64 * 65;        // [64][64]
    float* Ps = Vs + 64 * 64;        // [64][65]
    __shared__ int keep_s[64];

    const int tid = threadIdx.x;
    const int ty = tid >> 4, tx = tid & 15;
    const int b  = blockIdx.y;
    const int qt = gridDim.x - 1 - blockIdx.x;   // heavy tiles first
    const int q0 = qt * 64;

    if (tid < 64) keep_s[tid] = g_keep[q0 + tid];

    // load Q tile (row-major, +1 pad)
#pragma unroll
    for (int s = 0; s < 4; s++) {
        int c = s * 256 + tid;
        int q = c >> 4;
        int d = (c & 15) * 4;
        float4 v = *(const float4*)(g_Q + ((size_t)b * NKP + q0 + q) * HSX + d);
        Qs[q * 65 + d + 0] = v.x; Qs[q * 65 + d + 1] = v.y;
        Qs[q * 65 + d + 2] = v.z; Qs[q * 65 + d + 3] = v.w;
    }

    float o[4][4];
    float m_[4], l_[4];
#pragma unroll
    for (int i = 0; i < 4; i++) {
        m_[i] = -1e30f; l_[i] = 0.f;
#pragma unroll
        for (int j = 0; j < 4; j++) o[i][j] = 0.f;
    }

    __syncthreads();
    int kq[4];
#pragma unroll
    for (int i = 0; i < 4; i++) kq[i] = keep_s[4 * ty + i];
    const int nkt = keep_s[63] / 64 + 1;   // keep[] ascending -> last is max

    for (int kt = 0; kt < nkt; kt++) {
        const int t0 = kt * 64;
        // prefetch K/V to regs before the barrier
        float4 kv4[4], vv4[4];
#pragma unroll
        for (int s = 0; s < 4; s++) {
            int c = s * 256 + tid;
            int t = c >> 4;
            int d = (c & 15) * 4;
            size_t row = ((size_t)b * TT + t0 + t) * HSX + d;
            kv4[s] = *(const float4*)(g_K + row);
            vv4[s] = *(const float4*)(g_V + row);
        }
        __syncthreads();    // previous tile's Ps/Vs consumers are done
#pragma unroll
        for (int s = 0; s < 4; s++) {
            int c = s * 256 + tid;
            int t = c >> 4;
            int d = (c & 15) * 4;
            Ks[t * 65 + d + 0] = kv4[s].x; Ks[t * 65 + d + 1] = kv4[s].y;
            Ks[t * 65 + d + 2] = kv4[s].z; Ks[t * 65 + d + 3] = kv4[s].w;
            *(float4*)(Vs + t * 64 + d) = vv4[s];
        }
        __syncthreads();

        // S = Q @ K^T (4x4 micro-tile per thread)
        float sv[4][4];
#pragma unroll
        for (int i = 0; i < 4; i++)
#pragma unroll
            for (int j = 0; j < 4; j++) sv[i][j] = 0.f;
#pragma unroll 8
        for (int k = 0; k < 64; k++) {
            float qv[4], kvv[4];
#pragma unroll
            for (int i = 0; i < 4; i++) qv[i]  = Qs[(4 * ty + i) * 65 + k];
#pragma unroll
            for (int j = 0; j < 4; j++) kvv[j] = Ks[(4 * tx + j) * 65 + k];
#pragma unroll
            for (int i = 0; i < 4; i++)
#pragma unroll
                for (int j = 0; j < 4; j++) sv[i][j] += qv[i] * kvv[j];
        }
        // causal-ish mask: valid iff t <= keep[q]
#pragma unroll
        for (int i = 0; i < 4; i++)
#pragma unroll
            for (int j = 0; j < 4; j++)
                if (t0 + 4 * tx + j > kq[i]) sv[i][j] = -1e30f;

        // online softmax (row stats replicated across the 16 tx lanes)
#pragma unroll
        for (int i = 0; i < 4; i++) {
            float rmax = fmaxf(fmaxf(sv[i][0], sv[i][1]), fmaxf(sv[i][2], sv[i][3]));
#pragma unroll
            for (int w = 1; w < 16; w <<= 1)
                rmax = fmaxf(rmax, __shfl_xor_sync(0xffffffffu, rmax, w, 16));
            float mn = fmaxf(m_[i], rmax);
            float al = __expf(m_[i] - mn);   // underflows to 0 when m_ = -1e30
            m_[i] = mn;
            float rs = 0.f;
#pragma unroll
            for (int j = 0; j < 4; j++) {
                float p = __expf(sv[i][j] - mn);   // masked -> exp(-1e30-..) = 0
                Ps[(4 * ty + i) * 65 + 4 * tx + j] = p;
                rs += p;
            }
#pragma unroll
            for (int w = 1; w < 16; w <<= 1)
                rs += __shfl_xor_sync(0xffffffffu, rs, w, 16);
            l_[i] = l_[i] * al + rs;
#pragma unroll
            for (int j = 0; j < 4; j++) o[i][j] *= al;
        }
        __syncthreads();    // Ps visible

        // O += P @ V
#pragma unroll 8
        for (int t = 0; t < 64; t++) {
            float4 vv = *(const float4*)(Vs + t * 64 + 4 * tx);
#pragma unroll
            for (int i = 0; i < 4; i++) {
                float p = Ps[(4 * ty + i) * 65 + t];
                o[i][0] += p * vv.x; o[i][1] += p * vv.y;
                o[i][2] += p * vv.z; o[i][3] += p * vv.w;
            }
        }
    }

#pragma unroll
    for (int i = 0; i < 4; i++) {
        float inv = 1.f / l_[i];
        float4 r = make_float4(o[i][0] * inv, o[i][1] * inv,
                               o[i][2] * inv, o[i][3] * inv);
        *(float4*)(out + ((size_t)b * NKP + q0 + 4 * ty + i) * HSX + 4 * tx) = r;
    }
}

// ---------------- launcher ---------------------------------------------------
extern "C" void kernel_launch(void* const* d_in, const int* in_sizes, int n_in,
                              void* d_out, int out_size) {
    const float* x  = (const float*)d_in[0];
    const float* Wq = (const float*)d_in[1];
    const float* bq = (const float*)d_in[2];
    const float* Wk = (const float*)d_in[3];
    const float* bk = (const float*)d_in[4];
    const float* Wv = (const float*)d_in[5];
    const float* bv = (const float*)d_in[6];
    float* out = (float*)d_out;

    keep_kernel<<<(NKP + 255) / 256, 256>>>();
    proj_kv_kernel<<<(BB * TT) / 64, 256>>>(x, Wk, bk, Wv, bv);
    proj_q_kernel<<<(BB * NKP) / 64, 256>>>(x, Wq, bq);

    const size_t smem = (size_t)(64 * 65 * 3 + 64 * 64) * sizeof(float); // ~64.8 KB
    cudaFuncSetAttribute(attn_kernel,
                         cudaFuncAttributeMaxDynamicSharedMemorySize, (int)smem);
    dim3 g(NKP / 64, BB);
    attn_kernel<<<g, 256, smem>>>(out);
}

// round 2
// speedup vs baseline: 3.6957x; 3.6957x over previous
#include <cuda_runtime.h>
#include <math.h>

#define BB  8
#define TT  4096
#define CC  1024
#define HSX 64
#define NKP 2048
#define QSCALE 0.03125f

// ---------------- scratch ----------------------------------------------------
__device__ int   g_keep[NKP];
__device__ float g_K[(size_t)BB * TT * HSX];
__device__ float g_V[(size_t)BB * TT * HSX];
__device__ float g_Q[(size_t)BB * NKP * HSX];   // pre-scaled by 1/32

// ---------------- helpers -----------------------------------------------------
__device__ __forceinline__ unsigned f2tf(float f) {
    unsigned r; asm("cvt.rna.tf32.f32 %0, %1;" : "=r"(r) : "f"(f)); return r;
}
__device__ __forceinline__ void mma_tf32(float d[4], const unsigned a[4],
                                         const unsigned b[2]) {
    asm("mma.sync.aligned.m16n8k8.row.col.f32.tf32.tf32.f32 "
        "{%0,%1,%2,%3}, {%4,%5,%6,%7}, {%8,%9}, {%0,%1,%2,%3};"
        : "+f"(d[0]), "+f"(d[1]), "+f"(d[2]), "+f"(d[3])
        : "r"(a[0]), "r"(a[1]), "r"(a[2]), "r"(a[3]), "r"(b[0]), "r"(b[1]));
}

// ---------------- keep indices ------------------------------------------------
__global__ void keep_kernel() {
    int i = blockIdx.x * blockDim.x + threadIdx.x;
    if (i >= NKP) return;
    const int a = (TT + 3) / 4;
    int x = NKP - 1 - i;
    int v;
    if (x < a) v = TT - 1 - x;
    else {
        int k = x - a;
        double t = (3.0 / (double)a) * (double)k * (double)k + (double)a;
        v = TT - 1 - (int)ceil(t);
    }
    g_keep[i] = v;
}

// ---------------- K,V projection (tf32 MMA): M=128 tile, N=128 ---------------
__global__ __launch_bounds__(256) void proj_kv_kernel(
    const float* __restrict__ x,
    const float* __restrict__ Wk, const float* __restrict__ bk,
    const float* __restrict__ Wv, const float* __restrict__ bv)
{
    __shared__ unsigned Xs[128][36];
    __shared__ unsigned Ws[128][36];
    const int tid = threadIdx.x, lane = tid & 31, warp = tid >> 5;
    const int g = lane >> 2, tg = lane & 3;
    const int wm = warp >> 2, wn = warp & 3;      // 2 x 4 warp grid, 64x32 each
    const size_t m0 = (size_t)blockIdx.x * 128;

    float acc[4][4][4];
#pragma unroll
    for (int i = 0; i < 4; i++)
#pragma unroll
        for (int j = 0; j < 4; j++)
#pragma unroll
            for (int q = 0; q < 4; q++) acc[i][j][q] = 0.f;

    const int lrow = tid >> 3;            // 0..31
    const int lcol = (tid & 7) * 4;       // 0..28

    float4 xv[4], wv[4];
#pragma unroll
    for (int s = 0; s < 4; s++) {
        int r = lrow + s * 32;
        xv[s] = *(const float4*)(x + (m0 + r) * CC + lcol);
        const float* W = (r < 64) ? (Wk + (size_t)r * CC) : (Wv + (size_t)(r - 64) * CC);
        wv[s] = *(const float4*)(W + lcol);
    }

    for (int k0 = 0; k0 < CC; k0 += 32) {
        __syncthreads();
#pragma unroll
        for (int s = 0; s < 4; s++) {
            int r = lrow + s * 32;
            uint4 ux = {f2tf(xv[s].x), f2tf(xv[s].y), f2tf(xv[s].z), f2tf(xv[s].w)};
            uint4 uw = {f2tf(wv[s].x), f2tf(wv[s].y), f2tf(wv[s].z), f2tf(wv[s].w)};
            *(uint4*)&Xs[r][lcol] = ux;
            *(uint4*)&Ws[r][lcol] = uw;
        }
        __syncthreads();
        if (k0 + 32 < CC) {
            int k1 = k0 + 32;
#pragma unroll
            for (int s = 0; s < 4; s++) {
                int r = lrow + s * 32;
                xv[s] = *(const float4*)(x + (m0 + r) * CC + k1 + lcol);
                const float* W = (r < 64) ? (Wk + (size_t)r * CC)
                                          : (Wv + (size_t)(r - 64) * CC);
                wv[s] = *(const float4*)(W + k1 + lcol);
            }
        }
#pragma unroll
        for (int ks = 0; ks < 4; ks++) {
            const int kk = ks * 8;
            unsigned a[4][4], bf[4][2];
#pragma unroll
            for (int mi = 0; mi < 4; mi++) {
                int r = wm * 64 + mi * 16 + g;
                a[mi][0] = Xs[r][kk + tg];
                a[mi][1] = Xs[r + 8][kk + tg];
                a[mi][2] = Xs[r][kk + tg + 4];
                a[mi][3] = Xs[r + 8][kk + tg + 4];
            }
#pragma unroll
            for (int ni = 0; ni < 4; ni++) {
                int n = wn * 32 + ni * 8 + g;
                bf[ni][0] = Ws[n][kk + tg];
                bf[ni][1] = Ws[n][kk + tg + 4];
            }
#pragma unroll
            for (int mi = 0; mi < 4; mi++)
#pragma unroll
                for (int ni = 0; ni < 4; ni++)
                    mma_tf32(acc[mi][ni], a[mi], bf[ni]);
        }
    }

#pragma unroll
    for (int mi = 0; mi < 4; mi++) {
        size_t row = m0 + wm * 64 + mi * 16 + g;
#pragma unroll
        for (int ni = 0; ni < 4; ni++) {
            int col = wn * 32 + ni * 8 + 2 * tg;
            float* dst; int c; float b0, b1;
            if (col < 64) { dst = g_K; c = col;      b0 = bk[c]; b1 = bk[c + 1]; }
            else          { dst = g_V; c = col - 64; b0 = bv[c]; b1 = bv[c + 1]; }
            *(float2*)(dst + row * HSX + c) =
                make_float2(acc[mi][ni][0] + b0, acc[mi][ni][1] + b1);
            *(float2*)(dst + (row + 8) * HSX + c) =
                make_float2(acc[mi][ni][2] + b0, acc[mi][ni][3] + b1);
        }
    }
}

// ---------------- gathered Q projection (tf32 MMA): M=128, N=64 ---------------
__global__ __launch_bounds__(256) void proj_q_kernel(
    const float* __restrict__ x,
    const float* __restrict__ Wq, const float* __restrict__ bq)
{
    __shared__ unsigned Xs[128][36];
    __shared__ unsigned Ws[64][36];
    __shared__ int rows_s[128];
    const int tid = threadIdx.x, lane = tid & 31, warp = tid >> 5;
    const int g = lane >> 2, tg = lane & 3;
    const int wm = warp >> 1, wn = warp & 1;      // 4 x 2 warp grid, 32x32 each
    const size_t m0 = (size_t)blockIdx.x * 128;
    const int b = (int)(m0 / NKP);

    if (tid < 128) rows_s[tid] = g_keep[(m0 % NKP) + tid];
    __syncthreads();

    float acc[2][4][4];
#pragma unroll
    for (int i = 0; i < 2; i++)
#pragma unroll
        for (int j = 0; j < 4; j++)
#pragma unroll
            for (int q = 0; q < 4; q++) acc[i][j][q] = 0.f;

    const int lrow = tid >> 3, lcol = (tid & 7) * 4;
    const int wrow = tid >> 2;

    float4 xv[4], wv[2];
#pragma unroll
    for (int s = 0; s < 4; s++) {
        int r = lrow + s * 32;
        size_t xr = (size_t)b * TT + rows_s[r];
        xv[s] = *(const float4*)(x + xr * CC + lcol);
    }
#pragma unroll
    for (int s = 0; s < 2; s++) {
        int c = (tid & 3) * 4 + s * 16;
        wv[s] = *(const float4*)(Wq + (size_t)wrow * CC + c);
    }

    for (int k0 = 0; k0 < CC; k0 += 32) {
        __syncthreads();
#pragma unroll
        for (int s = 0; s < 4; s++) {
            int r = lrow + s * 32;
            uint4 u = {f2tf(xv[s].x), f2tf(xv[s].y), f2tf(xv[s].z), f2tf(xv[s].w)};
            *(uint4*)&Xs[r][lcol] = u;
        }
#pragma unroll
        for (int s = 0; s < 2; s++) {
            int c = (tid & 3) * 4 + s * 16;
            uint4 u = {f2tf(wv[s].x), f2tf(wv[s].y), f2tf(wv[s].z), f2tf(wv[s].w)};
            *(uint4*)&Ws[wrow][c] = u;
        }
        __syncthreads();
        if (k0 + 32 < CC) {
            int k1 = k0 + 32;
#pragma unroll
            for (int s = 0; s < 4; s++) {
                int r = lrow + s * 32;
                size_t xr = (size_t)b * TT + rows_s[r];
                xv[s] = *(const float4*)(x + xr * CC + k1 + lcol);
            }
#pragma unroll
            for (int s = 0; s < 2; s++) {
                int c = (tid & 3) * 4 + s * 16;
                wv[s] = *(const float4*)(Wq + (size_t)wrow * CC + k1 + c);
            }
        }
#pragma unroll
        for (int ks = 0; ks < 4; ks++) {
            const int kk = ks * 8;
            unsigned a[2][4], bf[4][2];
#pragma unroll
            for (int mi = 0; mi < 2; mi++) {
                int r = wm * 32 + mi * 16 + g;
                a[mi][0] = Xs[r][kk + tg];
                a[mi][1] = Xs[r + 8][kk + tg];
                a[mi][2] = Xs[r][kk + tg + 4];
                a[mi][3] = Xs[r + 8][kk + tg + 4];
            }
#pragma unroll
            for (int ni = 0; ni < 4; ni++) {
                int n = wn * 32 + ni * 8 + g;
                bf[ni][0] = Ws[n][kk + tg];
                bf[ni][1] = Ws[n][kk + tg + 4];
            }
#pragma unroll
            for (int mi = 0; mi < 2; mi++)
#pragma unroll
                for (int ni = 0; ni < 4; ni++)
                    mma_tf32(acc[mi][ni], a[mi], bf[ni]);
        }
    }

#pragma unroll
    for (int mi = 0; mi < 2; mi++) {
        size_t row = m0 + wm * 32 + mi * 16 + g;
#pragma unroll
        for (int ni = 0; ni < 4; ni++) {
            int c = wn * 32 + ni * 8 + 2 * tg;
            float b0 = bq[c], b1 = bq[c + 1];
            *(float2*)(g_Q + row * HSX + c) =
                make_float2((acc[mi][ni][0] + b0) * QSCALE, (acc[mi][ni][1] + b1) * QSCALE);
            *(float2*)(g_Q + (row + 8) * HSX + c) =
                make_float2((acc[mi][ni][2] + b0) * QSCALE, (acc[mi][ni][3] + b1) * QSCALE);
        }
    }
}

// ---------------- flash attention (tf32 MMA): 128 q-rows/block ---------------
__global__ __launch_bounds__(256) void attn_kernel(float* __restrict__ out) {
    extern __shared__ unsigned smu[];
    unsigned* Qs = smu;                 // [128][68]
    unsigned* Ks = Qs + 128 * 68;       // [64][68]
    unsigned* Vs = Ks + 64 * 68;        // [64][72]
    unsigned* Ps = Vs + 64 * 72;        // [128][68] (tf32 P)
    __shared__ int keep_s[128];

    const int tid = threadIdx.x, lane = tid & 31, warp = tid >> 5;
    const int g = lane >> 2, tg = lane & 3;
    const int b = blockIdx.y, q0 = blockIdx.x * 128;
    const int rbase = warp * 16;

    if (tid < 128) keep_s[tid] = g_keep[q0 + tid];

#pragma unroll
    for (int s = 0; s < 8; s++) {
        int idx = s * 256 + tid;
        int r = idx >> 4, c = (idx & 15) * 4;
        float4 v = *(const float4*)(g_Q + ((size_t)b * NKP + q0 + r) * HSX + c);
        uint4 u = {f2tf(v.x), f2tf(v.y), f2tf(v.z), f2tf(v.w)};
        *(uint4*)&Qs[r * 68 + c] = u;
    }

    float of[8][4];
#pragma unroll
    for (int i = 0; i < 8; i++)
#pragma unroll
        for (int j = 0; j < 4; j++) of[i][j] = 0.f;
    float m0_ = -1e30f, m1_ = -1e30f, l0 = 0.f, l1 = 0.f;

    __syncthreads();
    const int kq0 = keep_s[rbase + g], kq1 = keep_s[rbase + g + 8];
    const int nkt = keep_s[127] / 64 + 1;

    float4 kv4[4], vv4[4];
#pragma unroll
    for (int s = 0; s < 4; s++) {
        int idx = s * 256 + tid;
        int r = idx >> 4, c = (idx & 15) * 4;
        size_t rowoff = ((size_t)b * TT + r) * HSX + c;
        kv4[s] = *(const float4*)(g_K + rowoff);
        vv4[s] = *(const float4*)(g_V + rowoff);
    }

    for (int kt = 0; kt < nkt; kt++) {
        __syncthreads();
#pragma unroll
        for (int s = 0; s < 4; s++) {
            int idx = s * 256 + tid;
            int r = idx >> 4, c = (idx & 15) * 4;
            uint4 uk = {f2tf(kv4[s].x), f2tf(kv4[s].y), f2tf(kv4[s].z), f2tf(kv4[s].w)};
            uint4 uv = {f2tf(vv4[s].x), f2tf(vv4[s].y), f2tf(vv4[s].z), f2tf(vv4[s].w)};
            *(uint4*)&Ks[r * 68 + c] = uk;
            *(uint4*)&Vs[r * 72 + c] = uv;
        }
        __syncthreads();
        if (kt + 1 < nkt) {
            size_t t1 = (size_t)(kt + 1) * 64;
#pragma unroll
            for (int s = 0; s < 4; s++) {
                int idx = s * 256 + tid;
                int r = idx >> 4, c = (idx & 15) * 4;
                size_t rowoff = ((size_t)b * TT + t1 + r) * HSX + c;
                kv4[s] = *(const float4*)(g_K + rowoff);
                vv4[s] = *(const float4*)(g_V + rowoff);
            }
        }

        // ---- S = Q @ K^T
        float sacc[8][4];
#pragma unroll
        for (int i = 0; i < 8; i++)
#pragma unroll
            for (int j = 0; j < 4; j++) sacc[i][j] = 0.f;
#pragma unroll
        for (int kk = 0; kk < 64; kk += 8) {
            unsigned a[4];
            a[0] = Qs[(rbase + g) * 68 + kk + tg];
            a[1] = Qs[(rbase + g + 8) * 68 + kk + tg];
            a[2] = Qs[(rbase + g) * 68 + kk + tg + 4];
            a[3] = Qs[(rbase + g + 8) * 68 + kk + tg + 4];
#pragma unroll
            for (int ni = 0; ni < 8; ni++) {
                unsigned bf[2];
                bf[0] = Ks[(ni * 8 + g) * 68 + kk + tg];
                bf[1] = Ks[(ni * 8 + g) * 68 + kk + tg + 4];
                mma_tf32(sacc[ni], a, bf);
            }
        }

        // ---- mask + online softmax (rows r0 = rbase+g, r1 = r0+8)
        const int tcol = kt * 64 + 2 * tg;
        float rmax0 = -1e30f, rmax1 = -1e30f;
#pragma unroll
        for (int ni = 0; ni < 8; ni++) {
            int t = tcol + ni * 8;
            if (t > kq0)     sacc[ni][0] = -1e30f;
            if (t + 1 > kq0) sacc[ni][1] = -1e30f;
            if (t > kq1)     sacc[ni][2] = -1e30f;
            if (t + 1 > kq1) sacc[ni][3] = -1e30f;
            rmax0 = fmaxf(rmax0, fmaxf(sacc[ni][0], sacc[ni][1]));
            rmax1 = fmaxf(rmax1, fmaxf(sacc[ni][2], sacc[ni][3]));
        }
        rmax0 = fmaxf(rmax0, __shfl_xor_sync(0xffffffffu, rmax0, 1));
        rmax0 = fmaxf(rmax0, __shfl_xor_sync(0xffffffffu, rmax0, 2));
        rmax1 = fmaxf(rmax1, __shfl_xor_sync(0xffffffffu, rmax1, 1));
        rmax1 = fmaxf(rmax1, __shfl_xor_sync(0xffffffffu, rmax1, 2));
        float mn0 = fmaxf(m0_, rmax0), mn1 = fmaxf(m1_, rmax1);
        float al0 = __expf(m0_ - mn0), al1 = __expf(m1_ - mn1);
        m0_ = mn0; m1_ = mn1;
        float rs0 = 0.f, rs1 = 0.f;
#pragma unroll
        for (int ni = 0; ni < 8; ni++) {
            float p0 = __expf(sacc[ni][0] - mn0);
            float p1 = __expf(sacc[ni][1] - mn0);
            float p2 = __expf(sacc[ni][2] - mn1);
            float p3 = __expf(sacc[ni][3] - mn1);
            rs0 += p0 + p1; rs1 += p2 + p3;
            uint2 u0 = {f2tf(p0), f2tf(p1)};
            uint2 u1 = {f2tf(p2), f2tf(p3)};
            *(uint2*)&Ps[(rbase + g) * 68 + ni * 8 + 2 * tg] = u0;
            *(uint2*)&Ps[(rbase + g + 8) * 68 + ni * 8 + 2 * tg] = u1;
        }
        rs0 += __shfl_xor_sync(0xffffffffu, rs0, 1);
        rs0 += __shfl_xor_sync(0xffffffffu, rs0, 2);
        rs1 += __shfl_xor_sync(0xffffffffu, rs1, 1);
        rs1 += __shfl_xor_sync(0xffffffffu, rs1, 2);
        l0 = l0 * al0 + rs0;
        l1 = l1 * al1 + rs1;
#pragma unroll
        for (int ni = 0; ni < 8; ni++) {
            of[ni][0] *= al0; of[ni][1] *= al0;
            of[ni][2] *= al1; of[ni][3] *= al1;
        }
        __syncwarp();   // Ps region is per-warp private (rows rbase..rbase+15)

        // ---- O += P @ V
#pragma unroll
        for (int kk = 0; kk < 64; kk += 8) {
            unsigned a[4];
            a[0] = Ps[(rbase + g) * 68 + kk + tg];
            a[1] = Ps[(rbase + g + 8) * 68 + kk + tg];
            a[2] = Ps[(rbase + g) * 68 + kk + tg + 4];
            a[3] = Ps[(rbase + g + 8) * 68 + kk + tg + 4];
#pragma unroll
            for (int ni = 0; ni < 8; ni++) {
                unsigned bf[2];
                bf[0] = Vs[(kk + tg) * 72 + ni * 8 + g];
                bf[1] = Vs[(kk + tg + 4) * 72 + ni * 8 + g];
                mma_tf32(of[ni], a, bf);
            }
        }
        __syncwarp();
    }

    const float inv0 = 1.f / l0, inv1 = 1.f / l1;
    const size_t orow0 = ((size_t)b * NKP + q0 + rbase + g) * HSX;
    const size_t orow1 = orow0 + 8 * HSX;
#pragma unroll
    for (int ni = 0; ni < 8; ni++) {
        int c = ni * 8 + 2 * tg;
        *(float2*)(out + orow0 + c) = make_float2(of[ni][0] * inv0, of[ni][1] * inv0);
        *(float2*)(out + orow1 + c) = make_float2(of[ni][2] * inv1, of[ni][3] * inv1);
    }
}

// ---------------- launcher ----------------------------------------------------
extern "C" void kernel_launch(void* const* d_in, const int* in_sizes, int n_in,
                              void* d_out, int out_size) {
    const float* x  = (const float*)d_in[0];
    const float* Wq = (const float*)d_in[1];
    const float* bq = (const float*)d_in[2];
    const float* Wk = (const float*)d_in[3];
    const float* bk = (const float*)d_in[4];
    const float* Wv = (const float*)d_in[5];
    const float* bv = (const float*)d_in[6];
    float* out = (float*)d_out;

    keep_kernel<<<(NKP + 255) / 256, 256>>>();
    proj_kv_kernel<<<(BB * TT) / 128, 256>>>(x, Wk, bk, Wv, bv);
    proj_q_kernel<<<(BB * NKP) / 128, 256>>>(x, Wq, bq);

    const int smem = (128 * 68 + 64 * 68 + 64 * 72 + 128 * 68) * 4;  // 105472 B
    static int configured = -1;
    cudaFuncSetAttribute(attn_kernel,
                         cudaFuncAttributeMaxDynamicSharedMemorySize, smem);
    (void)configured;
    dim3 grd(NKP / 128, BB);
    attn_kernel<<<grd, 256, smem>>>(out);
}

// round 3
// speedup vs baseline: 3.7012x; 1.0015x over previous
#include <cuda_runtime.h>
#include <math.h>

#define BB  8
#define TT  4096
#define CC  1024
#define HSX 64
#define NKP 2048
#define QSCALE 0.03125f

// ---------------- scratch ----------------------------------------------------
__device__ int   g_keep[NKP];
__device__ float g_K[(size_t)BB * TT * HSX];
__device__ float g_V[(size_t)BB * TT * HSX];
__device__ float g_Q[(size_t)BB * NKP * HSX];   // pre-scaled by 1/32

// ---------------- helpers -----------------------------------------------------
__device__ __forceinline__ unsigned f2tf(float f) {
    unsigned r; asm("cvt.rna.tf32.f32 %0, %1;" : "=r"(r) : "f"(f)); return r;
}
__device__ __forceinline__ void mma_tf32(float d[4], const unsigned a[4],
                                         const unsigned b[2]) {
    asm("mma.sync.aligned.m16n8k8.row.col.f32.tf32.tf32.f32 "
        "{%0,%1,%2,%3}, {%4,%5,%6,%7}, {%8,%9}, {%0,%1,%2,%3};"
        : "+f"(d[0]), "+f"(d[1]), "+f"(d[2]), "+f"(d[3])
        : "r"(a[0]), "r"(a[1]), "r"(a[2]), "r"(a[3]), "r"(b[0]), "r"(b[1]));
}
__device__ __forceinline__ void cpa16(unsigned dst_smem, const void* src) {
    asm volatile("cp.async.ca.shared.global [%0], [%1], 16;"
                 :: "r"(dst_smem), "l"(src));
}

// ---------------- keep indices ------------------------------------------------
__global__ void keep_kernel() {
    int i = blockIdx.x * blockDim.x + threadIdx.x;
    if (i >= NKP) return;
    const int a = (TT + 3) / 4;
    int x = NKP - 1 - i;
    int v;
    if (x < a) v = TT - 1 - x;
    else {
        int k = x - a;
        double t = (3.0 / (double)a) * (double)k * (double)k + (double)a;
        v = TT - 1 - (int)ceil(t);
    }
    g_keep[i] = v;
}

// ---------------- K,V projection (tf32 MMA): M=128 tile, N=128 ---------------
__global__ __launch_bounds__(256) void proj_kv_kernel(
    const float* __restrict__ x,
    const float* __restrict__ Wk, const float* __restrict__ bk,
    const float* __restrict__ Wv, const float* __restrict__ bv)
{
    __shared__ unsigned Xs[128][36];
    __shared__ unsigned Ws[128][36];
    const int tid = threadIdx.x, lane = tid & 31, warp = tid >> 5;
    const int g = lane >> 2, tg = lane & 3;
    const int wm = warp >> 2, wn = warp & 3;
    const size_t m0 = (size_t)blockIdx.x * 128;

    float acc[4][4][4];
#pragma unroll
    for (int i = 0; i < 4; i++)
#pragma unroll
        for (int j = 0; j < 4; j++)
#pragma unroll
            for (int q = 0; q < 4; q++) acc[i][j][q] = 0.f;

    const int lrow = tid >> 3;
    const int lcol = (tid & 7) * 4;

    float4 xv[4], wv[4];
#pragma unroll
    for (int s = 0; s < 4; s++) {
        int r = lrow + s * 32;
        xv[s] = *(const float4*)(x + (m0 + r) * CC + lcol);
        const float* W = (r < 64) ? (Wk + (size_t)r * CC) : (Wv + (size_t)(r - 64) * CC);
        wv[s] = *(const float4*)(W + lcol);
    }

    for (int k0 = 0; k0 < CC; k0 += 32) {
        __syncthreads();
#pragma unroll
        for (int s = 0; s < 4; s++) {
            int r = lrow + s * 32;
            uint4 ux = {f2tf(xv[s].x), f2tf(xv[s].y), f2tf(xv[s].z), f2tf(xv[s].w)};
            uint4 uw = {f2tf(wv[s].x), f2tf(wv[s].y), f2tf(wv[s].z), f2tf(wv[s].w)};
            *(uint4*)&Xs[r][lcol] = ux;
            *(uint4*)&Ws[r][lcol] = uw;
        }
        __syncthreads();
        if (k0 + 32 < CC) {
            int k1 = k0 + 32;
#pragma unroll
            for (int s = 0; s < 4; s++) {
                int r = lrow + s * 32;
                xv[s] = *(const float4*)(x + (m0 + r) * CC + k1 + lcol);
                const float* W = (r < 64) ? (Wk + (size_t)r * CC)
                                          : (Wv + (size_t)(r - 64) * CC);
                wv[s] = *(const float4*)(W + k1 + lcol);
            }
        }
#pragma unroll
        for (int ks = 0; ks < 4; ks++) {
            const int kk = ks * 8;
            unsigned a[4][4], bf[4][2];
#pragma unroll
            for (int mi = 0; mi < 4; mi++) {
                int r = wm * 64 + mi * 16 + g;
                a[mi][0] = Xs[r][kk + tg];
                a[mi][1] = Xs[r + 8][kk + tg];
                a[mi][2] = Xs[r][kk + tg + 4];
                a[mi][3] = Xs[r + 8][kk + tg + 4];
            }
#pragma unroll
            for (int ni = 0; ni < 4; ni++) {
                int n = wn * 32 + ni * 8 + g;
                bf[ni][0] = Ws[n][kk + tg];
                bf[ni][1] = Ws[n][kk + tg + 4];
            }
#pragma unroll
            for (int mi = 0; mi < 4; mi++)
#pragma unroll
                for (int ni = 0; ni < 4; ni++)
                    mma_tf32(acc[mi][ni], a[mi], bf[ni]);
        }
    }

#pragma unroll
    for (int mi = 0; mi < 4; mi++) {
        size_t row = m0 + wm * 64 + mi * 16 + g;
#pragma unroll
        for (int ni = 0; ni < 4; ni++) {
            int col = wn * 32 + ni * 8 + 2 * tg;
            float* dst; int c; float b0, b1;
            if (col < 64) { dst = g_K; c = col;      b0 = bk[c]; b1 = bk[c + 1]; }
            else          { dst = g_V; c = col - 64; b0 = bv[c]; b1 = bv[c + 1]; }
            *(float2*)(dst + row * HSX + c) =
                make_float2(acc[mi][ni][0] + b0, acc[mi][ni][1] + b1);
            *(float2*)(dst + (row + 8) * HSX + c) =
                make_float2(acc[mi][ni][2] + b0, acc[mi][ni][3] + b1);
        }
    }
}

// ---------------- gathered Q projection (tf32 MMA): M=128, N=64 ---------------
__global__ __launch_bounds__(256) void proj_q_kernel(
    const float* __restrict__ x,
    const float* __restrict__ Wq, const float* __restrict__ bq)
{
    __shared__ unsigned Xs[128][36];
    __shared__ unsigned Ws[64][36];
    __shared__ int rows_s[128];
    const int tid = threadIdx.x, lane = tid & 31, warp = tid >> 5;
    const int g = lane >> 2, tg = lane & 3;
    const int wm = warp >> 1, wn = warp & 1;
    const size_t m0 = (size_t)blockIdx.x * 128;
    const int b = (int)(m0 / NKP);

    if (tid < 128) rows_s[tid] = g_keep[(m0 % NKP) + tid];
    __syncthreads();

    float acc[2][4][4];
#pragma unroll
    for (int i = 0; i < 2; i++)
#pragma unroll
        for (int j = 0; j < 4; j++)
#pragma unroll
            for (int q = 0; q < 4; q++) acc[i][j][q] = 0.f;

    const int lrow = tid >> 3, lcol = (tid & 7) * 4;
    const int wrow = tid >> 2;

    float4 xv[4], wv[2];
#pragma unroll
    for (int s = 0; s < 4; s++) {
        int r = lrow + s * 32;
        size_t xr = (size_t)b * TT + rows_s[r];
        xv[s] = *(const float4*)(x + xr * CC + lcol);
    }
#pragma unroll
    for (int s = 0; s < 2; s++) {
        int c = (tid & 3) * 4 + s * 16;
        wv[s] = *(const float4*)(Wq + (size_t)wrow * CC + c);
    }

    for (int k0 = 0; k0 < CC; k0 += 32) {
        __syncthreads();
#pragma unroll
        for (int s = 0; s < 4; s++) {
            int r = lrow + s * 32;
            uint4 u = {f2tf(xv[s].x), f2tf(xv[s].y), f2tf(xv[s].z), f2tf(xv[s].w)};
            *(uint4*)&Xs[r][lcol] = u;
        }
#pragma unroll
        for (int s = 0; s < 2; s++) {
            int c = (tid & 3) * 4 + s * 16;
            uint4 u = {f2tf(wv[s].x), f2tf(wv[s].y), f2tf(wv[s].z), f2tf(wv[s].w)};
            *(uint4*)&Ws[wrow][c] = u;
        }
        __syncthreads();
        if (k0 + 32 < CC) {
            int k1 = k0 + 32;
#pragma unroll
            for (int s = 0; s < 4; s++) {
                int r = lrow + s * 32;
                size_t xr = (size_t)b * TT + rows_s[r];
                xv[s] = *(const float4*)(x + xr * CC + k1 + lcol);
            }
#pragma unroll
            for (int s = 0; s < 2; s++) {
                int c = (tid & 3) * 4 + s * 16;
                wv[s] = *(const float4*)(Wq + (size_t)wrow * CC + k1 + c);
            }
        }
#pragma unroll
        for (int ks = 0; ks < 4; ks++) {
            const int kk = ks * 8;
            unsigned a[2][4], bf[4][2];
#pragma unroll
            for (int mi = 0; mi < 2; mi++) {
                int r = wm * 32 + mi * 16 + g;
                a[mi][0] = Xs[r][kk + tg];
                a[mi][1] = Xs[r + 8][kk + tg];
                a[mi][2] = Xs[r][kk + tg + 4];
                a[mi][3] = Xs[r + 8][kk + tg + 4];
            }
#pragma unroll
            for (int ni = 0; ni < 4; ni++) {
                int n = wn * 32 + ni * 8 + g;
                bf[ni][0] = Ws[n][kk + tg];
                bf[ni][1] = Ws[n][kk + tg + 4];
            }
#pragma unroll
            for (int mi = 0; mi < 2; mi++)
#pragma unroll
                for (int ni = 0; ni < 4; ni++)
                    mma_tf32(acc[mi][ni], a[mi], bf[ni]);
        }
    }

#pragma unroll
    for (int mi = 0; mi < 2; mi++) {
        size_t row = m0 + wm * 32 + mi * 16 + g;
#pragma unroll
        for (int ni = 0; ni < 4; ni++) {
            int c = wn * 32 + ni * 8 + 2 * tg;
            float b0 = bq[c], b1 = bq[c + 1];
            *(float2*)(g_Q + row * HSX + c) =
                make_float2((acc[mi][ni][0] + b0) * QSCALE, (acc[mi][ni][1] + b1) * QSCALE);
            *(float2*)(g_Q + (row + 8) * HSX + c) =
                make_float2((acc[mi][ni][2] + b0) * QSCALE, (acc[mi][ni][3] + b1) * QSCALE);
        }
    }
}

// ---------------- flash attention: 512 threads, n-split warp pairs -----------
// Warp w (w<8): rows 16w..16w+15, key cols 0..31.  Warp w+8: same rows, cols 32..63.
// smem: double-buffered K/V (cp.async) + softmax stat exchange.
#define BUF_U   8960            // Ks[64*68] + Vs[64*72] (unsigned units)
#define VS_OFF  4352            // Vs offset inside a buffer
#define STAT_U  (2 * BUF_U)     // stats base: rmax[2][128] then rs[2][128]
#define SMEM_U  (2 * BUF_U + 512)

__global__ __launch_bounds__(512) void attn_kernel(float* __restrict__ out) {
    extern __shared__ unsigned smu[];
    float* rmax_s = (float*)(smu + STAT_U);        // [2][128]
    float* rs_s   = (float*)(smu + STAT_U + 256);  // [2][128]
    __shared__ int keep_s[128];

    const int tid = threadIdx.x, lane = tid & 31, warp = tid >> 5;
    const int g = lane >> 2, tg = lane & 3;
    const int side = warp >> 3;                 // 0: keys 0..31, 1: keys 32..63
    const int rb = (warp & 7) * 16;             // q-row base of this warp
    const int b = blockIdx.y, q0 = blockIdx.x * 128;

    if (tid < 128) keep_s[tid] = g_keep[q0 + tid];

    // ---- stage Q into buffer region (pitch 68), convert to tf32
    unsigned* Qs = smu;
#pragma unroll
    for (int s = 0; s < 4; s++) {
        int idx = s * 512 + tid;
        int r = idx >> 4, c = (idx & 15) * 4;
        float4 v = *(const float4*)(g_Q + ((size_t)b * NKP + q0 + r) * HSX + c);
        uint4 u = {f2tf(v.x), f2tf(v.y), f2tf(v.z), f2tf(v.w)};
        *(uint4*)&Qs[r * 68 + c] = u;
    }
    __syncthreads();

    // ---- Q fragments to registers (once)
    unsigned qf[8][4];
#pragma unroll
    for (int k8 = 0; k8 < 8; k8++) {
        qf[k8][0] = Qs[(rb + g) * 68 + k8 * 8 + tg];
        qf[k8][1] = Qs[(rb + g + 8) * 68 + k8 * 8 + tg];
        qf[k8][2] = Qs[(rb + g) * 68 + k8 * 8 + tg + 4];
        qf[k8][3] = Qs[(rb + g + 8) * 68 + k8 * 8 + tg + 4];
    }
    const int kq0 = keep_s[rb + g], kq1 = keep_s[rb + g + 8];
    const int nkt = keep_s[127] / 64 + 1;
    __syncthreads();   // Qs region free for K/V buffers

    // smem byte base for cp.async addressing
    unsigned smem_b;
    asm("{ .reg .u64 t; cvta.to.shared.u64 t, %1; cvt.u32.u64 %0, t; }"
        : "=r"(smem_b) : "l"(smu));

    // per-thread staging coords: 2 float4 per matrix
    const int sr0 = tid >> 4, sc = (tid & 15) * 4;          // rows sr0, sr0+32

    // prologue: prefetch tile 0 into buf 0
    {
        const float* Kb = g_K + ((size_t)b * TT) * HSX;
        const float* Vb = g_V + ((size_t)b * TT) * HSX;
#pragma unroll
        for (int s = 0; s < 2; s++) {
            int r = sr0 + s * 32;
            cpa16(smem_b + (r * 68 + sc) * 4,            Kb + (size_t)r * HSX + sc);
            cpa16(smem_b + (VS_OFF + r * 72 + sc) * 4,   Vb + (size_t)r * HSX + sc);
        }
        asm volatile("cp.async.commit_group;");
    }

    float of[8][4];
#pragma unroll
    for (int i = 0; i < 8; i++)
#pragma unroll
        for (int j = 0; j < 4; j++) of[i][j] = 0.f;
    float m0_ = -1e30f, m1_ = -1e30f, l0 = 0.f, l1 = 0.f;

    for (int kt = 0; kt < nkt; kt++) {
        // prefetch next tile, wait for current
        if (kt + 1 < nkt) {
            const unsigned bo = ((kt + 1) & 1) * BUF_U;
            const size_t t1 = (size_t)(kt + 1) * 64;
            const float* Kb = g_K + ((size_t)b * TT + t1) * HSX;
            const float* Vb = g_V + ((size_t)b * TT + t1) * HSX;
#pragma unroll
            for (int s = 0; s < 2; s++) {
                int r = sr0 + s * 32;
                cpa16(smem_b + (bo + r * 68 + sc) * 4,          Kb + (size_t)r * HSX + sc);
                cpa16(smem_b + (bo + VS_OFF + r * 72 + sc) * 4, Vb + (size_t)r * HSX + sc);
            }
            asm volatile("cp.async.commit_group;");
            asm volatile("cp.async.wait_group 1;");
        } else {
            asm volatile("cp.async.wait_group 0;");
        }
        __syncthreads();

        const unsigned* Ks = smu + (kt & 1) * BUF_U;
        const unsigned* Vs = Ks + VS_OFF;

        // ---- S = Q @ K^T  (this warp's 32-key half)
        float sacc[4][4];
#pragma unroll
        for (int i = 0; i < 4; i++)
#pragma unroll
            for (int j = 0; j < 4; j++) sacc[i][j] = 0.f;
#pragma unroll
        for (int k8 = 0; k8 < 8; k8++) {
#pragma unroll
            for (int ni = 0; ni < 4; ni++) {
                unsigned bf[2];
                int kr = (side * 32 + ni * 8 + g) * 68 + k8 * 8;
                bf[0] = Ks[kr + tg];
                bf[1] = Ks[kr + tg + 4];
                mma_tf32(sacc[ni], qf[k8], bf);
            }
        }

        // ---- mask + row max (half)
        const int tcol = kt * 64 + side * 32 + 2 * tg;
        float rmax0 = -1e30f, rmax1 = -1e30f;
#pragma unroll
        for (int ni = 0; ni < 4; ni++) {
            int t = tcol + ni * 8;
            if (t > kq0)     sacc[ni][0] = -1e30f;
            if (t + 1 > kq0) sacc[ni][1] = -1e30f;
            if (t > kq1)     sacc[ni][2] = -1e30f;
            if (t + 1 > kq1) sacc[ni][3] = -1e30f;
            rmax0 = fmaxf(rmax0, fmaxf(sacc[ni][0], sacc[ni][1]));
            rmax1 = fmaxf(rmax1, fmaxf(sacc[ni][2], sacc[ni][3]));
        }
        rmax0 = fmaxf(rmax0, __shfl_xor_sync(0xffffffffu, rmax0, 1));
        rmax0 = fmaxf(rmax0, __shfl_xor_sync(0xffffffffu, rmax0, 2));
        rmax1 = fmaxf(rmax1, __shfl_xor_sync(0xffffffffu, rmax1, 1));
        rmax1 = fmaxf(rmax1, __shfl_xor_sync(0xffffffffu, rmax1, 2));
        if ((lane & 3) == 0) {
            rmax_s[side * 128 + rb + g]     = rmax0;
            rmax_s[side * 128 + rb + g + 8] = rmax1;
        }
        __syncthreads();

        const float mn0 = fmaxf(m0_, fmaxf(rmax_s[rb + g],     rmax_s[128 + rb + g]));
        const float mn1 = fmaxf(m1_, fmaxf(rmax_s[rb + g + 8], rmax_s[128 + rb + g + 8]));
        const float al0 = __expf(m0_ - mn0), al1 = __expf(m1_ - mn1);
        m0_ = mn0; m1_ = mn1;

        float rs0 = 0.f, rs1 = 0.f;
#pragma unroll
        for (int ni = 0; ni < 4; ni++) {
            sacc[ni][0] = __expf(sacc[ni][0] - mn0);
            sacc[ni][1] = __expf(sacc[ni][1] - mn0);
            sacc[ni][2] = __expf(sacc[ni][2] - mn1);
            sacc[ni][3] = __expf(sacc[ni][3] - mn1);
            rs0 += sacc[ni][0] + sacc[ni][1];
            rs1 += sacc[ni][2] + sacc[ni][3];
        }
        rs0 += __shfl_xor_sync(0xffffffffu, rs0, 1);
        rs0 += __shfl_xor_sync(0xffffffffu, rs0, 2);
        rs1 += __shfl_xor_sync(0xffffffffu, rs1, 1);
        rs1 += __shfl_xor_sync(0xffffffffu, rs1, 2);
        if ((lane & 3) == 0) {
            rs_s[side * 128 + rb + g]     = rs0;
            rs_s[side * 128 + rb + g + 8] = rs1;
        }
        __syncthreads();
        l0 = l0 * al0 + rs_s[rb + g]     + rs_s[128 + rb + g];
        l1 = l1 * al1 + rs_s[rb + g + 8] + rs_s[128 + rb + g + 8];
#pragma unroll
        for (int ni = 0; ni < 8; ni++) {
            of[ni][0] *= al0; of[ni][1] *= al0;
            of[ni][2] *= al1; of[ni][3] *= al1;
        }

        // ---- P via shuffles, then O += P @ V (this half's 32 key rows)
        const int srcA = (lane & ~3) | (tg >> 1);
        const int srcB = srcA + 2;
        const bool odd = (tg & 1);
#pragma unroll
        for (int kb = 0; kb < 4; kb++) {
            float v0 = __shfl_sync(0xffffffffu, sacc[kb][0], srcA);
            float v1 = __shfl_sync(0xffffffffu, sacc[kb][1], srcA);
            float w0 = __shfl_sync(0xffffffffu, sacc[kb][0], srcB);
            float w1 = __shfl_sync(0xffffffffu, sacc[kb][1], srcB);
            float u0 = __shfl_sync(0xffffffffu, sacc[kb][2], srcA);
            float u1 = __shfl_sync(0xffffffffu, sacc[kb][3], srcA);
            float x0 = __shfl_sync(0xffffffffu, sacc[kb][2], srcB);
            float x1 = __shfl_sync(0xffffffffu, sacc[kb][3], srcB);
            unsigned a[4];
            a[0] = f2tf(odd ? v1 : v0);
            a[1] = f2tf(odd ? u1 : u0);
            a[2] = f2tf(odd ? w1 : w0);
            a[3] = f2tf(odd ? x1 : x0);
            const int kr = side * 32 + kb * 8;
#pragma unroll
            for (int no = 0; no < 8; no++) {
                unsigned bf[2];
                bf[0] = Vs[(kr + tg) * 72 + no * 8 + g];
                bf[1] = Vs[(kr + tg + 4) * 72 + no * 8 + g];
                mma_tf32(of[no], a, bf);
            }
        }
        __syncthreads();   // everyone done with this buffer before reuse
    }

    // ---- combine warp-pair halves, normalize, store
    float* Os = (float*)smu;              // [128][66]
    if (side == 1) {
#pragma unroll
        for (int no = 0; no < 8; no++) {
            int c = no * 8 + 2 * tg;
            *(float2*)&Os[(rb + g) * 66 + c]     = make_float2(of[no][0], of[no][1]);
            *(float2*)&Os[(rb + g + 8) * 66 + c] = make_float2(of[no][2], of[no][3]);
        }
    }
    __syncthreads();
    if (side == 0) {
        const float inv0 = 1.f / l0, inv1 = 1.f / l1;
        const size_t orow0 = ((size_t)b * NKP + q0 + rb + g) * HSX;
        const size_t orow1 = orow0 + 8 * HSX;
#pragma unroll
        for (int no = 0; no < 8; no++) {
            int c = no * 8 + 2 * tg;
            float2 p0 = *(float2*)&Os[(rb + g) * 66 + c];
            float2 p1 = *(float2*)&Os[(rb + g + 8) * 66 + c];
            *(float2*)(out + orow0 + c) =
                make_float2((of[no][0] + p0.x) * inv0, (of[no][1] + p0.y) * inv0);
            *(float2*)(out + orow1 + c) =
                make_float2((of[no][2] + p1.x) * inv1, (of[no][3] + p1.y) * inv1);
        }
    }
}

// ---------------- launcher ----------------------------------------------------
extern "C" void kernel_launch(void* const* d_in, const int* in_sizes, int n_in,
                              void* d_out, int out_size) {
    const float* x  = (const float*)d_in[0];
    const float* Wq = (const float*)d_in[1];
    const float* bq = (const float*)d_in[2];
    const float* Wk = (const float*)d_in[3];
    const float* bk = (const float*)d_in[4];
    const float* Wv = (const float*)d_in[5];
    const float* bv = (const float*)d_in[6];
    float* out = (float*)d_out;

    keep_kernel<<<(NKP + 255) / 256, 256>>>();
    proj_kv_kernel<<<(BB * TT) / 128, 256>>>(x, Wk, bk, Wv, bv);
    proj_q_kernel<<<(BB * NKP) / 128, 256>>>(x, Wq, bq);

    const int smem = SMEM_U * 4;   // 73728 B
    cudaFuncSetAttribute(attn_kernel,
                         cudaFuncAttributeMaxDynamicSharedMemorySize, smem);
    dim3 grd(NKP / 128, BB);
    attn_kernel<<<grd, 512, smem>>>(out);
}

// round 4
// speedup vs baseline: 4.5468x; 1.2285x over previous
#include <cuda_runtime.h>
#include <math.h>

#define BB  8
#define TT  4096
#define CC  1024
#define HSX 64
#define NKP 2048
#define QSCALE 0.03125f
#define SPLITS 4

// ---------------- scratch ----------------------------------------------------
__device__ int   g_keep[NKP];
__device__ float g_K[(size_t)BB * TT * HSX];
__device__ float g_V[(size_t)BB * TT * HSX];
__device__ float g_Q[(size_t)BB * NKP * HSX];   // pre-scaled by 1/32
__device__ float g_Op[(size_t)BB * 32 * SPLITS * 64 * 64];   // partial O (16 MB)
__device__ float g_ml[(size_t)BB * 32 * SPLITS * 2 * 64];    // partial m,l

// ---------------- helpers -----------------------------------------------------
__device__ __forceinline__ unsigned f2tf(float f) {
    unsigned r; asm("cvt.rna.tf32.f32 %0, %1;" : "=r"(r) : "f"(f)); return r;
}
__device__ __forceinline__ void mma_tf32(float d[4], const unsigned a[4],
                                         const unsigned b[2]) {
    asm("mma.sync.aligned.m16n8k8.row.col.f32.tf32.tf32.f32 "
        "{%0,%1,%2,%3}, {%4,%5,%6,%7}, {%8,%9}, {%0,%1,%2,%3};"
        : "+f"(d[0]), "+f"(d[1]), "+f"(d[2]), "+f"(d[3])
        : "r"(a[0]), "r"(a[1]), "r"(a[2]), "r"(a[3]), "r"(b[0]), "r"(b[1]));
}
__device__ __forceinline__ void cpa16(unsigned dst_smem, const void* src) {
    asm volatile("cp.async.ca.shared.global [%0], [%1], 16;"
                 :: "r"(dst_smem), "l"(src));
}

// ---------------- keep indices ------------------------------------------------
__global__ void keep_kernel() {
    int i = blockIdx.x * blockDim.x + threadIdx.x;
    if (i >= NKP) return;
    const int a = (TT + 3) / 4;
    int x = NKP - 1 - i;
    int v;
    if (x < a) v = TT - 1 - x;
    else {
        int k = x - a;
        double t = (3.0 / (double)a) * (double)k * (double)k + (double)a;
        v = TT - 1 - (int)ceil(t);
    }
    g_keep[i] = v;
}

// ---------------- K,V projection (tf32 MMA) -----------------------------------
__global__ __launch_bounds__(256) void proj_kv_kernel(
    const float* __restrict__ x,
    const float* __restrict__ Wk, const float* __restrict__ bk,
    const float* __restrict__ Wv, const float* __restrict__ bv)
{
    __shared__ unsigned Xs[128][36];
    __shared__ unsigned Ws[128][36];
    const int tid = threadIdx.x, lane = tid & 31, warp = tid >> 5;
    const int g = lane >> 2, tg = lane & 3;
    const int wm = warp >> 2, wn = warp & 3;
    const size_t m0 = (size_t)blockIdx.x * 128;

    float acc[4][4][4];
#pragma unroll
    for (int i = 0; i < 4; i++)
#pragma unroll
        for (int j = 0; j < 4; j++)
#pragma unroll
            for (int q = 0; q < 4; q++) acc[i][j][q] = 0.f;

    const int lrow = tid >> 3;
    const int lcol = (tid & 7) * 4;

    float4 xv[4], wv[4];
#pragma unroll
    for (int s = 0; s < 4; s++) {
        int r = lrow + s * 32;
        xv[s] = *(const float4*)(x + (m0 + r) * CC + lcol);
        const float* W = (r < 64) ? (Wk + (size_t)r * CC) : (Wv + (size_t)(r - 64) * CC);
        wv[s] = *(const float4*)(W + lcol);
    }

    for (int k0 = 0; k0 < CC; k0 += 32) {
        __syncthreads();
#pragma unroll
        for (int s = 0; s < 4; s++) {
            int r = lrow + s * 32;
            uint4 ux = {f2tf(xv[s].x), f2tf(xv[s].y), f2tf(xv[s].z), f2tf(xv[s].w)};
            uint4 uw = {f2tf(wv[s].x), f2tf(wv[s].y), f2tf(wv[s].z), f2tf(wv[s].w)};
            *(uint4*)&Xs[r][lcol] = ux;
            *(uint4*)&Ws[r][lcol] = uw;
        }
        __syncthreads();
        if (k0 + 32 < CC) {
            int k1 = k0 + 32;
#pragma unroll
            for (int s = 0; s < 4; s++) {
                int r = lrow + s * 32;
                xv[s] = *(const float4*)(x + (m0 + r) * CC + k1 + lcol);
                const float* W = (r < 64) ? (Wk + (size_t)r * CC)
                                          : (Wv + (size_t)(r - 64) * CC);
                wv[s] = *(const float4*)(W + k1 + lcol);
            }
        }
#pragma unroll
        for (int ks = 0; ks < 4; ks++) {
            const int kk = ks * 8;
            unsigned a[4][4], bf[4][2];
#pragma unroll
            for (int mi = 0; mi < 4; mi++) {
                int r = wm * 64 + mi * 16 + g;
                a[mi][0] = Xs[r][kk + tg];
                a[mi][1] = Xs[r + 8][kk + tg];
                a[mi][2] = Xs[r][kk + tg + 4];
                a[mi][3] = Xs[r + 8][kk + tg + 4];
            }
#pragma unroll
            for (int ni = 0; ni < 4; ni++) {
                int n = wn * 32 + ni * 8 + g;
                bf[ni][0] = Ws[n][kk + tg];
                bf[ni][1] = Ws[n][kk + tg + 4];
            }
#pragma unroll
            for (int mi = 0; mi < 4; mi++)
#pragma unroll
                for (int ni = 0; ni < 4; ni++)
                    mma_tf32(acc[mi][ni], a[mi], bf[ni]);
        }
    }

#pragma unroll
    for (int mi = 0; mi < 4; mi++) {
        size_t row = m0 + wm * 64 + mi * 16 + g;
#pragma unroll
        for (int ni = 0; ni < 4; ni++) {
            int col = wn * 32 + ni * 8 + 2 * tg;
            float* dst; int c; float b0, b1;
            if (col < 64) { dst = g_K; c = col;      b0 = bk[c]; b1 = bk[c + 1]; }
            else          { dst = g_V; c = col - 64; b0 = bv[c]; b1 = bv[c + 1]; }
            *(float2*)(dst + row * HSX + c) =
                make_float2(acc[mi][ni][0] + b0, acc[mi][ni][1] + b1);
            *(float2*)(dst + (row + 8) * HSX + c) =
                make_float2(acc[mi][ni][2] + b0, acc[mi][ni][3] + b1);
        }
    }
}

// ---------------- gathered Q projection (tf32 MMA) -----------------------------
__global__ __launch_bounds__(256) void proj_q_kernel(
    const float* __restrict__ x,
    const float* __restrict__ Wq, const float* __restrict__ bq)
{
    __shared__ unsigned Xs[128][36];
    __shared__ unsigned Ws[64][36];
    __shared__ int rows_s[128];
    const int tid = threadIdx.x, lane = tid & 31, warp = tid >> 5;
    const int g = lane >> 2, tg = lane & 3;
    const int wm = warp >> 1, wn = warp & 1;
    const size_t m0 = (size_t)blockIdx.x * 128;
    const int b = (int)(m0 / NKP);

    if (tid < 128) rows_s[tid] = g_keep[(m0 % NKP) + tid];
    __syncthreads();

    float acc[2][4][4];
#pragma unroll
    for (int i = 0; i < 2; i++)
#pragma unroll
        for (int j = 0; j < 4; j++)
#pragma unroll
            for (int q = 0; q < 4; q++) acc[i][j][q] = 0.f;

    const int lrow = tid >> 3, lcol = (tid & 7) * 4;
    const int wrow = tid >> 2;

    float4 xv[4], wv[2];
#pragma unroll
    for (int s = 0; s < 4; s++) {
        int r = lrow + s * 32;
        size_t xr = (size_t)b * TT + rows_s[r];
        xv[s] = *(const float4*)(x + xr * CC + lcol);
    }
#pragma unroll
    for (int s = 0; s < 2; s++) {
        int c = (tid & 3) * 4 + s * 16;
        wv[s] = *(const float4*)(Wq + (size_t)wrow * CC + c);
    }

    for (int k0 = 0; k0 < CC; k0 += 32) {
        __syncthreads();
#pragma unroll
        for (int s = 0; s < 4; s++) {
            int r = lrow + s * 32;
            uint4 u = {f2tf(xv[s].x), f2tf(xv[s].y), f2tf(xv[s].z), f2tf(xv[s].w)};
            *(uint4*)&Xs[r][lcol] = u;
        }
#pragma unroll
        for (int s = 0; s < 2; s++) {
            int c = (tid & 3) * 4 + s * 16;
            uint4 u = {f2tf(wv[s].x), f2tf(wv[s].y), f2tf(wv[s].z), f2tf(wv[s].w)};
            *(uint4*)&Ws[wrow][c] = u;
        }
        __syncthreads();
        if (k0 + 32 < CC) {
            int k1 = k0 + 32;
#pragma unroll
            for (int s = 0; s < 4; s++) {
                int r = lrow + s * 32;
                size_t xr = (size_t)b * TT + rows_s[r];
                xv[s] = *(const float4*)(x + xr * CC + k1 + lcol);
            }
#pragma unroll
            for (int s = 0; s < 2; s++) {
                int c = (tid & 3) * 4 + s * 16;
                wv[s] = *(const float4*)(Wq + (size_t)wrow * CC + k1 + c);
            }
        }
#pragma unroll
        for (int ks = 0; ks < 4; ks++) {
            const int kk = ks * 8;
            unsigned a[2][4], bf[4][2];
#pragma unroll
            for (int mi = 0; mi < 2; mi++) {
                int r = wm * 32 + mi * 16 + g;
                a[mi][0] = Xs[r][kk + tg];
                a[mi][1] = Xs[r + 8][kk + tg];
                a[mi][2] = Xs[r][kk + tg + 4];
                a[mi][3] = Xs[r + 8][kk + tg + 4];
            }
#pragma unroll
            for (int ni = 0; ni < 4; ni++) {
                int n = wn * 32 + ni * 8 + g;
                bf[ni][0] = Ws[n][kk + tg];
                bf[ni][1] = Ws[n][kk + tg + 4];
            }
#pragma unroll
            for (int mi = 0; mi < 2; mi++)
#pragma unroll
                for (int ni = 0; ni < 4; ni++)
                    mma_tf32(acc[mi][ni], a[mi], bf[ni]);
        }
    }

#pragma unroll
    for (int mi = 0; mi < 2; mi++) {
        size_t row = m0 + wm * 32 + mi * 16 + g;
#pragma unroll
        for (int ni = 0; ni < 4; ni++) {
            int c = wn * 32 + ni * 8 + 2 * tg;
            float b0 = bq[c], b1 = bq[c + 1];
            *(float2*)(g_Q + row * HSX + c) =
                make_float2((acc[mi][ni][0] + b0) * QSCALE, (acc[mi][ni][1] + b1) * QSCALE);
            *(float2*)(g_Q + (row + 8) * HSX + c) =
                make_float2((acc[mi][ni][2] + b0) * QSCALE, (acc[mi][ni][3] + b1) * QSCALE);
        }
    }
}

// ---------------- flash attention: split-KV, 64 q-rows, 4 warps ---------------
// Block = (batch b, q-tile j of 64 rows, KV split s of 4). Each warp owns 16
// rows x full 64-key width -> softmax is warp-local. Writes partial O, m, l.
#define BUF_U   8960            // Ks[64*68] + Vs[64*72] (u32 units)
#define VS_OFF  4352
#define SMEM_U  (2 * BUF_U)

__global__ __launch_bounds__(128, 3) void attn_kernel() {
    extern __shared__ unsigned smu[];
    __shared__ int keep_s[64];

    const int tid = threadIdx.x, lane = tid & 31, warp = tid >> 5;
    const int g = lane >> 2, tg = lane & 3;
    const int b = blockIdx.y;
    const int j = 31 - (blockIdx.x >> 2);      // heavy q-tiles first
    const int s = blockIdx.x & 3;
    const int q0 = j * 64;
    const int rb = warp * 16;
    const int unit = (b * 32 + j) * SPLITS + s;

    if (tid < 64) keep_s[tid] = g_keep[q0 + tid];
    __syncthreads();
    const int nkt = keep_s[63] / 64 + 1;
    const int csz = (nkt + SPLITS - 1) / SPLITS;
    const int kt0 = s * csz;
    const int kt1 = min(nkt, kt0 + csz);
    const int kq0 = keep_s[rb + g], kq1 = keep_s[rb + g + 8];

    if (kt0 >= kt1) {                          // empty split
        if ((lane & 3) == 0) {
            g_ml[(size_t)unit * 128 + rb + g]          = -1e30f;
            g_ml[(size_t)unit * 128 + rb + g + 8]      = -1e30f;
            g_ml[(size_t)unit * 128 + 64 + rb + g]     = 0.f;
            g_ml[(size_t)unit * 128 + 64 + rb + g + 8] = 0.f;
        }
        return;
    }

    // ---- stage Q (64x64) into smem, convert to tf32, pull frags to regs
    unsigned* Qs = smu;
#pragma unroll
    for (int t = 0; t < 8; t++) {
        int idx = t * 128 + tid;
        int r = idx >> 4, c = (idx & 15) * 4;
        float4 v = *(const float4*)(g_Q + ((size_t)b * NKP + q0 + r) * HSX + c);
        uint4 u = {f2tf(v.x), f2tf(v.y), f2tf(v.z), f2tf(v.w)};
        *(uint4*)&Qs[r * 68 + c] = u;
    }
    __syncthreads();
    unsigned qf[8][4];
#pragma unroll
    for (int k8 = 0; k8 < 8; k8++) {
        qf[k8][0] = Qs[(rb + g) * 68 + k8 * 8 + tg];
        qf[k8][1] = Qs[(rb + g + 8) * 68 + k8 * 8 + tg];
        qf[k8][2] = Qs[(rb + g) * 68 + k8 * 8 + tg + 4];
        qf[k8][3] = Qs[(rb + g + 8) * 68 + k8 * 8 + tg + 4];
    }
    __syncthreads();

    unsigned smem_b;
    asm("{ .reg .u64 t; cvta.to.shared.u64 t, %1; cvt.u32.u64 %0, t; }"
        : "=r"(smem_b) : "l"(smu));

    const int sr0 = tid >> 4, sc = (tid & 15) * 4;

    // prologue: prefetch tile kt0 into buffer 0
    {
        const float* Kb = g_K + ((size_t)b * TT + (size_t)kt0 * 64) * HSX;
        const float* Vb = g_V + ((size_t)b * TT + (size_t)kt0 * 64) * HSX;
#pragma unroll
        for (int t = 0; t < 8; t++) {
            int r = sr0 + t * 8;
            cpa16(smem_b + (r * 68 + sc) * 4,          Kb + (size_t)r * HSX + sc);
            cpa16(smem_b + (VS_OFF + r * 72 + sc) * 4, Vb + (size_t)r * HSX + sc);
        }
        asm volatile("cp.async.commit_group;");
    }

    float of[8][4];
#pragma unroll
    for (int i = 0; i < 8; i++)
#pragma unroll
        for (int jj = 0; jj < 4; jj++) of[i][jj] = 0.f;
    float m0_ = -1e30f, m1_ = -1e30f, l0 = 0.f, l1 = 0.f;

    for (int kt = kt0; kt < kt1; kt++) {
        if (kt + 1 < kt1) {
            const unsigned bo = ((kt + 1 - kt0) & 1) * BUF_U;
            const float* Kb = g_K + ((size_t)b * TT + (size_t)(kt + 1) * 64) * HSX;
            const float* Vb = g_V + ((size_t)b * TT + (size_t)(kt + 1) * 64) * HSX;
#pragma unroll
            for (int t = 0; t < 8; t++) {
                int r = sr0 + t * 8;
                cpa16(smem_b + (bo + r * 68 + sc) * 4,          Kb + (size_t)r * HSX + sc);
                cpa16(smem_b + (bo + VS_OFF + r * 72 + sc) * 4, Vb + (size_t)r * HSX + sc);
            }
            asm volatile("cp.async.commit_group;");
            asm volatile("cp.async.wait_group 1;");
        } else {
            asm volatile("cp.async.wait_group 0;");
        }
        __syncthreads();

        const unsigned* Ks = smu + ((kt - kt0) & 1) * BUF_U;
        const unsigned* Vs = Ks + VS_OFF;

        // ---- S = Q @ K^T (16 rows x 64 keys)
        float sacc[8][4];
#pragma unroll
        for (int i = 0; i < 8; i++)
#pragma unroll
            for (int jj = 0; jj < 4; jj++) sacc[i][jj] = 0.f;
#pragma unroll
        for (int k8 = 0; k8 < 8; k8++) {
#pragma unroll
            for (int ni = 0; ni < 8; ni++) {
                unsigned bf[2];
                int kr = (ni * 8 + g) * 68 + k8 * 8;
                bf[0] = Ks[kr + tg];
                bf[1] = Ks[kr + tg + 4];
                mma_tf32(sacc[ni], qf[k8], bf);
            }
        }

        // ---- mask + warp-local online softmax
        const int tcol = kt * 64 + 2 * tg;
        float rmax0 = -1e30f, rmax1 = -1e30f;
#pragma unroll
        for (int ni = 0; ni < 8; ni++) {
            int t = tcol + ni * 8;
            if (t > kq0)     sacc[ni][0] = -1e30f;
            if (t + 1 > kq0) sacc[ni][1] = -1e30f;
            if (t > kq1)     sacc[ni][2] = -1e30f;
            if (t + 1 > kq1) sacc[ni][3] = -1e30f;
            rmax0 = fmaxf(rmax0, fmaxf(sacc[ni][0], sacc[ni][1]));
            rmax1 = fmaxf(rmax1, fmaxf(sacc[ni][2], sacc[ni][3]));
        }
        rmax0 = fmaxf(rmax0, __shfl_xor_sync(0xffffffffu, rmax0, 1));
        rmax0 = fmaxf(rmax0, __shfl_xor_sync(0xffffffffu, rmax0, 2));
        rmax1 = fmaxf(rmax1, __shfl_xor_sync(0xffffffffu, rmax1, 1));
        rmax1 = fmaxf(rmax1, __shfl_xor_sync(0xffffffffu, rmax1, 2));
        const float mn0 = fmaxf(m0_, rmax0), mn1 = fmaxf(m1_, rmax1);
        // guard: if a row is fully masked so far, use 0 as the exp base so all
        // its exps underflow to 0 instead of exp(0)=1
        const float mb0 = (mn0 == -1e30f) ? 0.f : mn0;
        const float mb1 = (mn1 == -1e30f) ? 0.f : mn1;
        const float al0 = __expf(m0_ - mb0), al1 = __expf(m1_ - mb1);
        m0_ = mn0; m1_ = mn1;

        float rs0 = 0.f, rs1 = 0.f;
#pragma unroll
        for (int ni = 0; ni < 8; ni++) {
            sacc[ni][0] = __expf(sacc[ni][0] - mb0);
            sacc[ni][1] = __expf(sacc[ni][1] - mb0);
            sacc[ni][2] = __expf(sacc[ni][2] - mb1);
            sacc[ni][3] = __expf(sacc[ni][3] - mb1);
            rs0 += sacc[ni][0] + sacc[ni][1];
            rs1 += sacc[ni][2] + sacc[ni][3];
        }
        rs0 += __shfl_xor_sync(0xffffffffu, rs0, 1);
        rs0 += __shfl_xor_sync(0xffffffffu, rs0, 2);
        rs1 += __shfl_xor_sync(0xffffffffu, rs1, 1);
        rs1 += __shfl_xor_sync(0xffffffffu, rs1, 2);
        l0 = l0 * al0 + rs0;
        l1 = l1 * al1 + rs1;
#pragma unroll
        for (int ni = 0; ni < 8; ni++) {
            of[ni][0] *= al0; of[ni][1] *= al0;
            of[ni][2] *= al1; of[ni][3] *= al1;
        }

        // ---- P via shuffles, then O += P @ V
        const int srcA = (lane & ~3) | (tg >> 1);
        const int srcB = srcA + 2;
        const bool odd = (tg & 1);
#pragma unroll
        for (int kb = 0; kb < 8; kb++) {
            float v0 = __shfl_sync(0xffffffffu, sacc[kb][0], srcA);
            float v1 = __shfl_sync(0xffffffffu, sacc[kb][1], srcA);
            float w0 = __shfl_sync(0xffffffffu, sacc[kb][0], srcB);
            float w1 = __shfl_sync(0xffffffffu, sacc[kb][1], srcB);
            float u0 = __shfl_sync(0xffffffffu, sacc[kb][2], srcA);
            float u1 = __shfl_sync(0xffffffffu, sacc[kb][3], srcA);
            float x0 = __shfl_sync(0xffffffffu, sacc[kb][2], srcB);
            float x1 = __shfl_sync(0xffffffffu, sacc[kb][3], srcB);
            unsigned a[4];
            a[0] = f2tf(odd ? v1 : v0);
            a[1] = f2tf(odd ? u1 : u0);
            a[2] = f2tf(odd ? w1 : w0);
            a[3] = f2tf(odd ? x1 : x0);
            const int kr = kb * 8;
#pragma unroll
            for (int no = 0; no < 8; no++) {
                unsigned bf[2];
                bf[0] = Vs[(kr + tg) * 72 + no * 8 + g];
                bf[1] = Vs[(kr + tg + 4) * 72 + no * 8 + g];
                mma_tf32(of[no], a, bf);
            }
        }
        __syncthreads();   // all warps done with this buffer before next prefetch
    }

    // ---- write partial O (unnormalized) and m, l
    const size_t obase = (size_t)unit * 64;
#pragma unroll
    for (int no = 0; no < 8; no++) {
        int c = no * 8 + 2 * tg;
        *(float2*)(g_Op + (obase + rb + g) * 64 + c) =
            make_float2(of[no][0], of[no][1]);
        *(float2*)(g_Op + (obase + rb + 8 + g) * 64 + c) =
            make_float2(of[no][2], of[no][3]);
    }
    if ((lane & 3) == 0) {
        g_ml[(size_t)unit * 128 + rb + g]          = m0_;
        g_ml[(size_t)unit * 128 + rb + g + 8]      = m1_;
        g_ml[(size_t)unit * 128 + 64 + rb + g]     = l0;
        g_ml[(size_t)unit * 128 + 64 + rb + g + 8] = l1;
    }
}

// ---------------- combine: merge 4 KV-split partials --------------------------
__global__ __launch_bounds__(128) void combine_kernel(float* __restrict__ out) {
    const int b = blockIdx.y, j = blockIdx.x;
    const int tid = threadIdx.x;
    const int r = tid >> 1, h = (tid & 1) * 32;
    const size_t ub = (size_t)(b * 32 + j) * SPLITS;

    float m[SPLITS], l[SPLITS];
    float mstar = -1e30f;
#pragma unroll
    for (int s = 0; s < SPLITS; s++) {
        m[s] = g_ml[(ub + s) * 128 + r];
        l[s] = g_ml[(ub + s) * 128 + 64 + r];
        mstar = fmaxf(mstar, m[s]);
    }
    float c[SPLITS], L = 0.f;
#pragma unroll
    for (int s = 0; s < SPLITS; s++) {
        c[s] = __expf(m[s] - mstar);
        L += l[s] * c[s];
    }
    const float inv = 1.f / L;
#pragma unroll
    for (int s = 0; s < SPLITS; s++) c[s] *= inv;

    const size_t orow = ((size_t)b * NKP + j * 64 + r) * HSX + h;
#pragma unroll
    for (int d = 0; d < 32; d += 4) {
        float4 acc = make_float4(0.f, 0.f, 0.f, 0.f);
#pragma unroll
        for (int s = 0; s < SPLITS; s++) {
            float4 v = *(const float4*)(g_Op + ((ub + s) * 64 + r) * 64 + h + d);
            acc.x += c[s] * v.x; acc.y += c[s] * v.y;
            acc.z += c[s] * v.z; acc.w += c[s] * v.w;
        }
        *(float4*)(out + orow + d) = acc;
    }
}

// ---------------- launcher ------------------------------------------------------
extern "C" void kernel_launch(void* const* d_in, const int* in_sizes, int n_in,
                              void* d_out, int out_size) {
    const float* x  = (const float*)d_in[0];
    const float* Wq = (const float*)d_in[1];
    const float* bq = (const float*)d_in[2];
    const float* Wk = (const float*)d_in[3];
    const float* bk = (const float*)d_in[4];
    const float* Wv = (const float*)d_in[5];
    const float* bv = (const float*)d_in[6];
    float* out = (float*)d_out;

    keep_kernel<<<(NKP + 255) / 256, 256>>>();
    proj_kv_kernel<<<(BB * TT) / 128, 256>>>(x, Wk, bk, Wv, bv);
    proj_q_kernel<<<(BB * NKP) / 128, 256>>>(x, Wq, bq);

    const int smem = SMEM_U * 4;   // 71680 B
    cudaFuncSetAttribute(attn_kernel,
                         cudaFuncAttributeMaxDynamicSharedMemorySize, smem);
    dim3 grd(32 * SPLITS, BB);
    attn_kernel<<<grd, 128, smem>>>();

    dim3 gc(32, BB);
    combine_kernel<<<gc, 128>>>(out);
}

// round 5
// speedup vs baseline: 6.5457x; 1.4396x over previous
#include <cuda_runtime.h>
#include <cuda_fp16.h>
#include <math.h>

#define BB  8
#define TT  4096
#define CC  1024
#define HSX 64
#define NKP 2048
#define QSCALE 0.03125f
#define SPLITS 4

// ---------------- scratch ----------------------------------------------------
__device__ int    g_keep[NKP];
__device__ __half g_Kh[(size_t)BB * TT * HSX];          // K, row-major half
__device__ __half g_Vt[(size_t)BB * HSX * TT];          // V transposed [b][d][t]
__device__ __half g_Qh[(size_t)BB * NKP * HSX];         // Q half, pre-scaled
__device__ float  g_Op[(size_t)BB * 32 * SPLITS * 64 * 64];
__device__ float  g_ml[(size_t)BB * 32 * SPLITS * 2 * 64];

// ---------------- helpers -----------------------------------------------------
__device__ __forceinline__ unsigned h2(float lo, float hi) {
    unsigned r;
    asm("cvt.rn.f16x2.f32 %0, %1, %2;" : "=r"(r) : "f"(hi), "f"(lo));
    return r;
}
__device__ __forceinline__ void mma_f16(float d[4], const unsigned a[4],
                                        const unsigned b[2]) {
    asm("mma.sync.aligned.m16n8k16.row.col.f32.f16.f16.f32 "
        "{%0,%1,%2,%3}, {%4,%5,%6,%7}, {%8,%9}, {%0,%1,%2,%3};"
        : "+f"(d[0]), "+f"(d[1]), "+f"(d[2]), "+f"(d[3])
        : "r"(a[0]), "r"(a[1]), "r"(a[2]), "r"(a[3]), "r"(b[0]), "r"(b[1]));
}
__device__ __forceinline__ void cpa16(unsigned dst_smem, const void* src) {
    asm volatile("cp.async.ca.shared.global [%0], [%1], 16;"
                 :: "r"(dst_smem), "l"(src));
}

// ---------------- keep indices ------------------------------------------------
__global__ void keep_kernel() {
    int i = blockIdx.x * blockDim.x + threadIdx.x;
    if (i >= NKP) return;
    const int a = (TT + 3) / 4;
    int x = NKP - 1 - i;
    int v;
    if (x < a) v = TT - 1 - x;
    else {
        int k = x - a;
        double t = (3.0 / (double)a) * (double)k * (double)k + (double)a;
        v = TT - 1 - (int)ceil(t);
    }
    g_keep[i] = v;
}

// ---------------- K,V projection (fp16 MMA): M=128 tile, N=128 ----------------
__global__ __launch_bounds__(256) void proj_kv_kernel(
    const float* __restrict__ x,
    const float* __restrict__ Wk, const float* __restrict__ bk,
    const float* __restrict__ Wv, const float* __restrict__ bv)
{
    __shared__ unsigned Xs[128][20];   // 128 x 40 half, pitch 20 u32
    __shared__ unsigned Ws[128][20];
    const int tid = threadIdx.x, lane = tid & 31, warp = tid >> 5;
    const int g = lane >> 2, tg = lane & 3;
    const int wm = warp >> 2, wn = warp & 3;
    const size_t m0 = (size_t)blockIdx.x * 128;
    const int bidx = blockIdx.x >> 5;          // 32 blocks per batch

    float acc[4][4][4];
#pragma unroll
    for (int i = 0; i < 4; i++)
#pragma unroll
        for (int j = 0; j < 4; j++)
#pragma unroll
            for (int q = 0; q < 4; q++) acc[i][j][q] = 0.f;

    const int lrow = tid >> 3;
    const int lcol = (tid & 7) * 4;
    const int lcu  = (tid & 7) * 2;

    float4 xv[4], wv[4];
#pragma unroll
    for (int s = 0; s < 4; s++) {
        int r = lrow + s * 32;
        xv[s] = *(const float4*)(x + (m0 + r) * CC + lcol);
        const float* W = (r < 64) ? (Wk + (size_t)r * CC) : (Wv + (size_t)(r - 64) * CC);
        wv[s] = *(const float4*)(W + lcol);
    }

    for (int k0 = 0; k0 < CC; k0 += 32) {
        __syncthreads();
#pragma unroll
        for (int s = 0; s < 4; s++) {
            int r = lrow + s * 32;
            Xs[r][lcu]     = h2(xv[s].x, xv[s].y);
            Xs[r][lcu + 1] = h2(xv[s].z, xv[s].w);
            Ws[r][lcu]     = h2(wv[s].x, wv[s].y);
            Ws[r][lcu + 1] = h2(wv[s].z, wv[s].w);
        }
        __syncthreads();
        if (k0 + 32 < CC) {
            int k1 = k0 + 32;
#pragma unroll
            for (int s = 0; s < 4; s++) {
                int r = lrow + s * 32;
                xv[s] = *(const float4*)(x + (m0 + r) * CC + k1 + lcol);
                const float* W = (r < 64) ? (Wk + (size_t)r * CC)
                                          : (Wv + (size_t)(r - 64) * CC);
                wv[s] = *(const float4*)(W + k1 + lcol);
            }
        }
#pragma unroll
        for (int kc = 0; kc < 2; kc++) {
            const int kk = kc * 8;
            unsigned a[4][4], bf[4][2];
#pragma unroll
            for (int mi = 0; mi < 4; mi++) {
                int r = wm * 64 + mi * 16 + g;
                a[mi][0] = Xs[r][kk + tg];
                a[mi][1] = Xs[r + 8][kk + tg];
                a[mi][2] = Xs[r][kk + tg + 4];
                a[mi][3] = Xs[r + 8][kk + tg + 4];
            }
#pragma unroll
            for (int ni = 0; ni < 4; ni++) {
                int n = wn * 32 + ni * 8 + g;
                bf[ni][0] = Ws[n][kk + tg];
                bf[ni][1] = Ws[n][kk + tg + 4];
            }
#pragma unroll
            for (int mi = 0; mi < 4; mi++)
#pragma unroll
                for (int ni = 0; ni < 4; ni++)
                    mma_f16(acc[mi][ni], a[mi], bf[ni]);
        }
    }

    const int t_in = (int)(m0 % TT);
#pragma unroll
    for (int mi = 0; mi < 4; mi++) {
        size_t row = m0 + wm * 64 + mi * 16 + g;
        int t = t_in + wm * 64 + mi * 16 + g;
#pragma unroll
        for (int ni = 0; ni < 4; ni++) {
            int col = wn * 32 + ni * 8 + 2 * tg;
            if (col < 64) {
                float b0 = bk[col], b1 = bk[col + 1];
                ((unsigned*)g_Kh)[row * 32 + col / 2] =
                    h2(acc[mi][ni][0] + b0, acc[mi][ni][1] + b1);
                ((unsigned*)g_Kh)[(row + 8) * 32 + col / 2] =
                    h2(acc[mi][ni][2] + b0, acc[mi][ni][3] + b1);
            } else {
                int c = col - 64;
                float b0 = bv[c], b1 = bv[c + 1];
                size_t base0 = ((size_t)bidx * HSX + c) * TT;
                size_t base1 = base0 + TT;
                g_Vt[base0 + t]     = __float2half_rn(acc[mi][ni][0] + b0);
                g_Vt[base1 + t]     = __float2half_rn(acc[mi][ni][1] + b1);
                g_Vt[base0 + t + 8] = __float2half_rn(acc[mi][ni][2] + b0);
                g_Vt[base1 + t + 8] = __float2half_rn(acc[mi][ni][3] + b1);
            }
        }
    }
}

// ---------------- gathered Q projection (fp16 MMA): M=128, N=64 ---------------
__global__ __launch_bounds__(256) void proj_q_kernel(
    const float* __restrict__ x,
    const float* __restrict__ Wq, const float* __restrict__ bq)
{
    __shared__ unsigned Xs[128][20];
    __shared__ unsigned Ws[64][20];
    __shared__ int rows_s[128];
    const int tid = threadIdx.x, lane = tid & 31, warp = tid >> 5;
    const int g = lane >> 2, tg = lane & 3;
    const int wm = warp >> 1, wn = warp & 1;
    const size_t m0 = (size_t)blockIdx.x * 128;
    const int b = (int)(m0 / NKP);

    if (tid < 128) rows_s[tid] = g_keep[(m0 % NKP) + tid];
    __syncthreads();

    float acc[2][4][4];
#pragma unroll
    for (int i = 0; i < 2; i++)
#pragma unroll
        for (int j = 0; j < 4; j++)
#pragma unroll
            for (int q = 0; q < 4; q++) acc[i][j][q] = 0.f;

    const int lrow = tid >> 3, lcol = (tid & 7) * 4, lcu = (tid & 7) * 2;
    const int wrow = tid >> 2;

    float4 xv[4], wv[2];
#pragma unroll
    for (int s = 0; s < 4; s++) {
        int r = lrow + s * 32;
        size_t xr = (size_t)b * TT + rows_s[r];
        xv[s] = *(const float4*)(x + xr * CC + lcol);
    }
#pragma unroll
    for (int s = 0; s < 2; s++) {
        int c = (tid & 3) * 4 + s * 16;
        wv[s] = *(const float4*)(Wq + (size_t)wrow * CC + c);
    }

    for (int k0 = 0; k0 < CC; k0 += 32) {
        __syncthreads();
#pragma unroll
        for (int s = 0; s < 4; s++) {
            int r = lrow + s * 32;
            Xs[r][lcu]     = h2(xv[s].x, xv[s].y);
            Xs[r][lcu + 1] = h2(xv[s].z, xv[s].w);
        }
#pragma unroll
        for (int s = 0; s < 2; s++) {
            int cu = (tid & 3) * 2 + s * 8;
            Ws[wrow][cu]     = h2(wv[s].x, wv[s].y);
            Ws[wrow][cu + 1] = h2(wv[s].z, wv[s].w);
        }
        __syncthreads();
        if (k0 + 32 < CC) {
            int k1 = k0 + 32;
#pragma unroll
            for (int s = 0; s < 4; s++) {
                int r = lrow + s * 32;
                size_t xr = (size_t)b * TT + rows_s[r];
                xv[s] = *(const float4*)(x + xr * CC + k1 + lcol);
            }
#pragma unroll
            for (int s = 0; s < 2; s++) {
                int c = (tid & 3) * 4 + s * 16;
                wv[s] = *(const float4*)(Wq + (size_t)wrow * CC + k1 + c);
            }
        }
#pragma unroll
        for (int kc = 0; kc < 2; kc++) {
            const int kk = kc * 8;
            unsigned a[2][4], bf[4][2];
#pragma unroll
            for (int mi = 0; mi < 2; mi++) {
                int r = wm * 32 + mi * 16 + g;
                a[mi][0] = Xs[r][kk + tg];
                a[mi][1] = Xs[r + 8][kk + tg];
                a[mi][2] = Xs[r][kk + tg + 4];
                a[mi][3] = Xs[r + 8][kk + tg + 4];
            }
#pragma unroll
            for (int ni = 0; ni < 4; ni++) {
                int n = wn * 32 + ni * 8 + g;
                bf[ni][0] = Ws[n][kk + tg];
                bf[ni][1] = Ws[n][kk + tg + 4];
            }
#pragma unroll
            for (int mi = 0; mi < 2; mi++)
#pragma unroll
                for (int ni = 0; ni < 4; ni++)
                    mma_f16(acc[mi][ni], a[mi], bf[ni]);
        }
    }

#pragma unroll
    for (int mi = 0; mi < 2; mi++) {
        size_t row = m0 + wm * 32 + mi * 16 + g;
#pragma unroll
        for (int ni = 0; ni < 4; ni++) {
            int c = wn * 32 + ni * 8 + 2 * tg;
            float b0 = bq[c], b1 = bq[c + 1];
            ((unsigned*)g_Qh)[row * 32 + c / 2] =
                h2((acc[mi][ni][0] + b0) * QSCALE, (acc[mi][ni][1] + b1) * QSCALE);
            ((unsigned*)g_Qh)[(row + 8) * 32 + c / 2] =
                h2((acc[mi][ni][2] + b0) * QSCALE, (acc[mi][ni][3] + b1) * QSCALE);
        }
    }
}

// ---------------- flash attention: fp16 MMA, split-KV -------------------------
// smem buffer: Ks[64][72]h (9216B) + Vt[64][72]h (9216B); two buffers.
#define BUF_U   4608            // u32 units per buffer
#define VS_OFF  2304
#define SMEM_B  (2 * BUF_U * 4) // 36864 bytes

__global__ __launch_bounds__(128, 4) void attn_kernel() {
    extern __shared__ unsigned smu[];
    __shared__ int keep_s[64];

    const int tid = threadIdx.x, lane = tid & 31, warp = tid >> 5;
    const int g = lane >> 2, tg = lane & 3;
    const int b = blockIdx.y;
    const int j = 31 - (blockIdx.x >> 2);      // heavy q-tiles first
    const int s = blockIdx.x & 3;
    const int q0 = j * 64;
    const int rb = warp * 16;
    const int unit = (b * 32 + j) * SPLITS + s;

    if (tid < 64) keep_s[tid] = g_keep[q0 + tid];
    __syncthreads();
    const int nkt = keep_s[63] / 64 + 1;
    const int csz = (nkt + SPLITS - 1) / SPLITS;
    const int kt0 = s * csz;
    const int kt1 = min(nkt, kt0 + csz);
    const int kq0 = keep_s[rb + g], kq1 = keep_s[rb + g + 8];

    if (kt0 >= kt1) {
        if ((lane & 3) == 0) {
            g_ml[(size_t)unit * 128 + rb + g]          = -1e30f;
            g_ml[(size_t)unit * 128 + rb + g + 8]      = -1e30f;
            g_ml[(size_t)unit * 128 + 64 + rb + g]     = 0.f;
            g_ml[(size_t)unit * 128 + 64 + rb + g + 8] = 0.f;
        }
        return;
    }

    unsigned smem_b;
    asm("{ .reg .u64 t; cvta.to.shared.u64 t, %1; cvt.u32.u64 %0, t; }"
        : "=r"(smem_b) : "l"(smu));

    // ---- stage Q (64x64 half) via cp.async into buffer 0 region
#pragma unroll
    for (int i = 0; i < 4; i++) {
        int gid = tid + i * 128;
        int r = gid >> 3, gc = gid & 7;
        cpa16(smem_b + (r * 36 + gc * 4) * 4,
              g_Qh + ((size_t)b * NKP + q0 + r) * HSX + gc * 8);
    }
    asm volatile("cp.async.commit_group;");
    asm volatile("cp.async.wait_group 0;");
    __syncthreads();

    unsigned qf[4][4];
#pragma unroll
    for (int kc = 0; kc < 4; kc++) {
        qf[kc][0] = smu[(rb + g) * 36 + kc * 8 + tg];
        qf[kc][1] = smu[(rb + g + 8) * 36 + kc * 8 + tg];
        qf[kc][2] = smu[(rb + g) * 36 + kc * 8 + tg + 4];
        qf[kc][3] = smu[(rb + g + 8) * 36 + kc * 8 + tg + 4];
    }
    __syncthreads();   // Q region free for K/V buffers

    // ---- prologue: prefetch tile kt0 into buffer 0
    {
        const __half* Kb = g_Kh + ((size_t)b * TT + (size_t)kt0 * 64) * HSX;
        const __half* Vb = g_Vt + (size_t)b * HSX * TT + (size_t)kt0 * 64;
#pragma unroll
        for (int i = 0; i < 4; i++) {
            int gid = tid + i * 128;
            int r = gid >> 3, gc = gid & 7;
            cpa16(smem_b + (r * 36 + gc * 4) * 4,            Kb + (size_t)r * HSX + gc * 8);
            cpa16(smem_b + ((VS_OFF + r * 36 + gc * 4)) * 4, Vb + (size_t)r * TT + gc * 8);
        }
        asm volatile("cp.async.commit_group;");
    }

    float of[8][4];
#pragma unroll
    for (int i = 0; i < 8; i++)
#pragma unroll
        for (int jj = 0; jj < 4; jj++) of[i][jj] = 0.f;
    float m0_ = -1e30f, m1_ = -1e30f, l0 = 0.f, l1 = 0.f;

    for (int kt = kt0; kt < kt1; kt++) {
        if (kt + 1 < kt1) {
            const unsigned bo = ((kt + 1 - kt0) & 1) * BUF_U;
            const __half* Kb = g_Kh + ((size_t)b * TT + (size_t)(kt + 1) * 64) * HSX;
            const __half* Vb = g_Vt + (size_t)b * HSX * TT + (size_t)(kt + 1) * 64;
#pragma unroll
            for (int i = 0; i < 4; i++) {
                int gid = tid + i * 128;
                int r = gid >> 3, gc = gid & 7;
                cpa16(smem_b + (bo + r * 36 + gc * 4) * 4,          Kb + (size_t)r * HSX + gc * 8);
                cpa16(smem_b + (bo + VS_OFF + r * 36 + gc * 4) * 4, Vb + (size_t)r * TT + gc * 8);
            }
            asm volatile("cp.async.commit_group;");
            asm volatile("cp.async.wait_group 1;");
        } else {
            asm volatile("cp.async.wait_group 0;");
        }
        __syncthreads();

        const unsigned* Ks = smu + ((kt - kt0) & 1) * BUF_U;
        const unsigned* Vs = Ks + VS_OFF;

        // ---- S = Q @ K^T (16 rows x 64 keys), fp16 k16
        float sacc[8][4];
#pragma unroll
        for (int i = 0; i < 8; i++)
#pragma unroll
            for (int jj = 0; jj < 4; jj++) sacc[i][jj] = 0.f;
#pragma unroll
        for (int kc = 0; kc < 4; kc++) {
#pragma unroll
            for (int ni = 0; ni < 8; ni++) {
                unsigned bf[2];
                int kr = (ni * 8 + g) * 36 + kc * 8;
                bf[0] = Ks[kr + tg];
                bf[1] = Ks[kr + tg + 4];
                mma_f16(sacc[ni], qf[kc], bf);
            }
        }

        // ---- mask + warp-local online softmax
        const int tcol = kt * 64 + 2 * tg;
        float rmax0 = -1e30f, rmax1 = -1e30f;
#pragma unroll
        for (int ni = 0; ni < 8; ni++) {
            int t = tcol + ni * 8;
            if (t > kq0)     sacc[ni][0] = -1e30f;
            if (t + 1 > kq0) sacc[ni][1] = -1e30f;
            if (t > kq1)     sacc[ni][2] = -1e30f;
            if (t + 1 > kq1) sacc[ni][3] = -1e30f;
            rmax0 = fmaxf(rmax0, fmaxf(sacc[ni][0], sacc[ni][1]));
            rmax1 = fmaxf(rmax1, fmaxf(sacc[ni][2], sacc[ni][3]));
        }
        rmax0 = fmaxf(rmax0, __shfl_xor_sync(0xffffffffu, rmax0, 1));
        rmax0 = fmaxf(rmax0, __shfl_xor_sync(0xffffffffu, rmax0, 2));
        rmax1 = fmaxf(rmax1, __shfl_xor_sync(0xffffffffu, rmax1, 1));
        rmax1 = fmaxf(rmax1, __shfl_xor_sync(0xffffffffu, rmax1, 2));
        const float mn0 = fmaxf(m0_, rmax0), mn1 = fmaxf(m1_, rmax1);
        const float mb0 = (mn0 == -1e30f) ? 0.f : mn0;
        const float mb1 = (mn1 == -1e30f) ? 0.f : mn1;
        const float al0 = __expf(m0_ - mb0), al1 = __expf(m1_ - mb1);
        m0_ = mn0; m1_ = mn1;

        float rs0 = 0.f, rs1 = 0.f;
        unsigned pA[8], pB[8];     // pA: rows g; pB: rows g+8 (half2 pairs)
#pragma unroll
        for (int ni = 0; ni < 8; ni++) {
            sacc[ni][0] = __expf(sacc[ni][0] - mb0);
            sacc[ni][1] = __expf(sacc[ni][1] - mb0);
            sacc[ni][2] = __expf(sacc[ni][2] - mb1);
            sacc[ni][3] = __expf(sacc[ni][3] - mb1);
            rs0 += sacc[ni][0] + sacc[ni][1];
            rs1 += sacc[ni][2] + sacc[ni][3];
            pA[ni] = h2(sacc[ni][0], sacc[ni][1]);
            pB[ni] = h2(sacc[ni][2], sacc[ni][3]);
        }
        rs0 += __shfl_xor_sync(0xffffffffu, rs0, 1);
        rs0 += __shfl_xor_sync(0xffffffffu, rs0, 2);
        rs1 += __shfl_xor_sync(0xffffffffu, rs1, 1);
        rs1 += __shfl_xor_sync(0xffffffffu, rs1, 2);
        l0 = l0 * al0 + rs0;
        l1 = l1 * al1 + rs1;
#pragma unroll
        for (int ni = 0; ni < 8; ni++) {
            of[ni][0] *= al0; of[ni][1] *= al0;
            of[ni][2] *= al1; of[ni][3] *= al1;
        }

        // ---- O += P @ V  (A fragments straight from registers)
#pragma unroll
        for (int kb = 0; kb < 4; kb++) {
            unsigned a[4];
            a[0] = pA[2 * kb];
            a[1] = pB[2 * kb];
            a[2] = pA[2 * kb + 1];
            a[3] = pB[2 * kb + 1];
#pragma unroll
            for (int no = 0; no < 8; no++) {
                unsigned bf[2];
                int vr = (no * 8 + g) * 36 + kb * 8;
                bf[0] = Vs[vr + tg];
                bf[1] = Vs[vr + tg + 4];
                mma_f16(of[no], a, bf);
            }
        }
        __syncthreads();
    }

    // ---- write partial O and m, l
    const size_t obase = (size_t)unit * 64;
#pragma unroll
    for (int no = 0; no < 8; no++) {
        int c = no * 8 + 2 * tg;
        *(float2*)(g_Op + (obase + rb + g) * 64 + c) =
            make_float2(of[no][0], of[no][1]);
        *(float2*)(g_Op + (obase + rb + 8 + g) * 64 + c) =
            make_float2(of[no][2], of[no][3]);
    }
    if ((lane & 3) == 0) {
        g_ml[(size_t)unit * 128 + rb + g]          = m0_;
        g_ml[(size_t)unit * 128 + rb + g + 8]      = m1_;
        g_ml[(size_t)unit * 128 + 64 + rb + g]     = l0;
        g_ml[(size_t)unit * 128 + 64 + rb + g + 8] = l1;
    }
}

// ---------------- combine: merge 4 KV-split partials --------------------------
__global__ __launch_bounds__(128) void combine_kernel(float* __restrict__ out) {
    const int b = blockIdx.y, j = blockIdx.x;
    const int tid = threadIdx.x;
    const int r = tid >> 1, h = (tid & 1) * 32;
    const size_t ub = (size_t)(b * 32 + j) * SPLITS;

    float m[SPLITS], l[SPLITS];
    float mstar = -1e30f;
#pragma unroll
    for (int s = 0; s < SPLITS; s++) {
        m[s] = g_ml[(ub + s) * 128 + r];
        l[s] = g_ml[(ub + s) * 128 + 64 + r];
        mstar = fmaxf(mstar, m[s]);
    }
    float c[SPLITS], L = 0.f;
#pragma unroll
    for (int s = 0; s < SPLITS; s++) {
        c[s] = __expf(m[s] - mstar);
        L += l[s] * c[s];
    }
    const float inv = 1.f / L;
#pragma unroll
    for (int s = 0; s < SPLITS; s++) c[s] *= inv;

    const size_t orow = ((size_t)b * NKP + j * 64 + r) * HSX + h;
#pragma unroll
    for (int d = 0; d < 32; d += 4) {
        float4 acc = make_float4(0.f, 0.f, 0.f, 0.f);
#pragma unroll
        for (int s = 0; s < SPLITS; s++) {
            float4 v = *(const float4*)(g_Op + ((ub + s) * 64 + r) * 64 + h + d);
            acc.x += c[s] * v.x; acc.y += c[s] * v.y;
            acc.z += c[s] * v.z; acc.w += c[s] * v.w;
        }
        *(float4*)(out + orow + d) = acc;
    }
}

// ---------------- launcher ------------------------------------------------------
extern "C" void kernel_launch(void* const* d_in, const int* in_sizes, int n_in,
                              void* d_out, int out_size) {
    const float* x  = (const float*)d_in[0];
    const float* Wq = (const float*)d_in[1];
    const float* bq = (const float*)d_in[2];
    const float* Wk = (const float*)d_in[3];
    const float* bk = (const float*)d_in[4];
    const float* Wv = (const float*)d_in[5];
    const float* bv = (const float*)d_in[6];
    float* out = (float*)d_out;

    keep_kernel<<<(NKP + 255) / 256, 256>>>();
    proj_kv_kernel<<<(BB * TT) / 128, 256>>>(x, Wk, bk, Wv, bv);
    proj_q_kernel<<<(BB * NKP) / 128, 256>>>(x, Wq, bq);

    cudaFuncSetAttribute(attn_kernel,
                         cudaFuncAttributeMaxDynamicSharedMemorySize, SMEM_B);
    dim3 grd(32 * SPLITS, BB);
    attn_kernel<<<grd, 128, SMEM_B>>>();

    dim3 gc(32, BB);
    combine_kernel<<<gc, 128>>>(out);
}

// round 6
// speedup vs baseline: 6.9023x; 1.0545x over previous
#include <cuda_runtime.h>
#include <cuda_fp16.h>
#include <math.h>

#define BB  8
#define TT  4096
#define CC  1024
#define HSX 64
#define NKP 2048
#define QSCALE 0.03125f
#define SPLITS 4

// ---------------- scratch ----------------------------------------------------
__device__ int    g_keep[NKP];
__device__ __half g_Kh[(size_t)BB * TT * HSX];          // K, row-major half
__device__ __half g_Vt[(size_t)BB * HSX * TT];          // V transposed [b][d][t]
__device__ __half g_Qh[(size_t)BB * TT * HSX];          // Q half for ALL rows, pre-scaled
__device__ float  g_Op[(size_t)BB * 32 * SPLITS * 64 * 64];
__device__ float  g_ml[(size_t)BB * 32 * SPLITS * 2 * 64];

// ---------------- helpers -----------------------------------------------------
__device__ __forceinline__ unsigned h2(float lo, float hi) {
    unsigned r;
    asm("cvt.rn.f16x2.f32 %0, %1, %2;" : "=r"(r) : "f"(hi), "f"(lo));
    return r;
}
__device__ __forceinline__ void mma_f16(float d[4], const unsigned a[4],
                                        const unsigned b[2]) {
    asm("mma.sync.aligned.m16n8k16.row.col.f32.f16.f16.f32 "
        "{%0,%1,%2,%3}, {%4,%5,%6,%7}, {%8,%9}, {%0,%1,%2,%3};"
        : "+f"(d[0]), "+f"(d[1]), "+f"(d[2]), "+f"(d[3])
        : "r"(a[0]), "r"(a[1]), "r"(a[2]), "r"(a[3]), "r"(b[0]), "r"(b[1]));
}
__device__ __forceinline__ void cpa16(unsigned dst_smem, const void* src) {
    asm volatile("cp.async.ca.shared.global [%0], [%1], 16;"
                 :: "r"(dst_smem), "l"(src));
}

// ---------------- keep indices ------------------------------------------------
__global__ void keep_kernel() {
    int i = blockIdx.x * blockDim.x + threadIdx.x;
    if (i >= NKP) return;
    const int a = (TT + 3) / 4;
    int x = NKP - 1 - i;
    int v;
    if (x < a) v = TT - 1 - x;
    else {
        int k = x - a;
        double t = (3.0 / (double)a) * (double)k * (double)k + (double)a;
        v = TT - 1 - (int)ceil(t);
    }
    g_keep[i] = v;
}

// ---------------- fused Q,K,V projection: X[128,1024] @ W^T[1024,192] --------
// W rows: 0..63 = Wq, 64..127 = Wk, 128..191 = Wv. Q computed for ALL rows.
__global__ __launch_bounds__(256) void proj_kernel(
    const float* __restrict__ x,
    const float* __restrict__ Wq, const float* __restrict__ bq,
    const float* __restrict__ Wk, const float* __restrict__ bk,
    const float* __restrict__ Wv, const float* __restrict__ bv)
{
    __shared__ unsigned Xs[128][20];   // 128 x 40 half
    __shared__ unsigned Ws[192][20];   // 192 x 40 half
    const int tid = threadIdx.x, lane = tid & 31, warp = tid >> 5;
    const int g = lane >> 2, tg = lane & 3;
    const int wm = warp >> 2, wn = warp & 3;      // 2 x 4 warps, tile 64 x 48
    const size_t m0 = (size_t)blockIdx.x * 128;
    const int bidx = blockIdx.x >> 5;             // 32 blocks per batch
    const int t_in = (int)(m0 % TT);

    float acc[4][6][4];
#pragma unroll
    for (int i = 0; i < 4; i++)
#pragma unroll
        for (int j = 0; j < 6; j++)
#pragma unroll
            for (int q = 0; q < 4; q++) acc[i][j][q] = 0.f;

    const int xr = tid >> 3, xc4 = (tid & 7) * 4, xcu = (tid & 7) * 2;

    float4 xv[4], wv[6];
#pragma unroll
    for (int s = 0; s < 4; s++)
        xv[s] = *(const float4*)(x + (m0 + xr + s * 32) * CC + xc4);
#pragma unroll
    for (int s = 0; s < 6; s++) {
        int idx = tid + s * 256;
        int r = idx >> 3, c4 = (idx & 7) * 4;
        const float* W = (r < 64) ? (Wq + (size_t)r * CC)
                       : (r < 128) ? (Wk + (size_t)(r - 64) * CC)
                                   : (Wv + (size_t)(r - 128) * CC);
        wv[s] = *(const float4*)(W + c4);
    }

    for (int k0 = 0; k0 < CC; k0 += 32) {
        __syncthreads();
#pragma unroll
        for (int s = 0; s < 4; s++) {
            int r = xr + s * 32;
            Xs[r][xcu]     = h2(xv[s].x, xv[s].y);
            Xs[r][xcu + 1] = h2(xv[s].z, xv[s].w);
        }
#pragma unroll
        for (int s = 0; s < 6; s++) {
            int idx = tid + s * 256;
            int r = idx >> 3, cu = (idx & 7) * 2;
            Ws[r][cu]     = h2(wv[s].x, wv[s].y);
            Ws[r][cu + 1] = h2(wv[s].z, wv[s].w);
        }
        __syncthreads();
        if (k0 + 32 < CC) {
            int k1 = k0 + 32;
#pragma unroll
            for (int s = 0; s < 4; s++)
                xv[s] = *(const float4*)(x + (m0 + xr + s * 32) * CC + k1 + xc4);
#pragma unroll
            for (int s = 0; s < 6; s++) {
                int idx = tid + s * 256;
                int r = idx >> 3, c4 = (idx & 7) * 4;
                const float* W = (r < 64) ? (Wq + (size_t)r * CC)
                               : (r < 128) ? (Wk + (size_t)(r - 64) * CC)
                                           : (Wv + (size_t)(r - 128) * CC);
                wv[s] = *(const float4*)(W + k1 + c4);
            }
        }
#pragma unroll
        for (int kc = 0; kc < 2; kc++) {
            const int kk = kc * 8;
            unsigned a[4][4], bf[6][2];
#pragma unroll
            for (int mi = 0; mi < 4; mi++) {
                int r = wm * 64 + mi * 16 + g;
                a[mi][0] = Xs[r][kk + tg];
                a[mi][1] = Xs[r + 8][kk + tg];
                a[mi][2] = Xs[r][kk + tg + 4];
                a[mi][3] = Xs[r + 8][kk + tg + 4];
            }
#pragma unroll
            for (int ni = 0; ni < 6; ni++) {
                int n = wn * 48 + ni * 8 + g;
                bf[ni][0] = Ws[n][kk + tg];
                bf[ni][1] = Ws[n][kk + tg + 4];
            }
#pragma unroll
            for (int mi = 0; mi < 4; mi++)
#pragma unroll
                for (int ni = 0; ni < 6; ni++)
                    mma_f16(acc[mi][ni], a[mi], bf[ni]);
        }
    }

#pragma unroll
    for (int mi = 0; mi < 4; mi++) {
        size_t row = m0 + wm * 64 + mi * 16 + g;
        int t = t_in + wm * 64 + mi * 16 + g;
#pragma unroll
        for (int ni = 0; ni < 6; ni++) {
            int col = wn * 48 + ni * 8 + 2 * tg;
            if (col < 64) {                         // Q (scaled)
                float b0 = bq[col], b1 = bq[col + 1];
                ((unsigned*)g_Qh)[row * 32 + col / 2] =
                    h2((acc[mi][ni][0] + b0) * QSCALE, (acc[mi][ni][1] + b1) * QSCALE);
                ((unsigned*)g_Qh)[(row + 8) * 32 + col / 2] =
                    h2((acc[mi][ni][2] + b0) * QSCALE, (acc[mi][ni][3] + b1) * QSCALE);
            } else if (col < 128) {                 // K
                int c = col - 64;
                float b0 = bk[c], b1 = bk[c + 1];
                ((unsigned*)g_Kh)[row * 32 + c / 2] =
                    h2(acc[mi][ni][0] + b0, acc[mi][ni][1] + b1);
                ((unsigned*)g_Kh)[(row + 8) * 32 + c / 2] =
                    h2(acc[mi][ni][2] + b0, acc[mi][ni][3] + b1);
            } else {                                // V (transposed store)
                int c = col - 128;
                float b0 = bv[c], b1 = bv[c + 1];
                size_t base0 = ((size_t)bidx * HSX + c) * TT;
                size_t base1 = base0 + TT;
                g_Vt[base0 + t]     = __float2half_rn(acc[mi][ni][0] + b0);
                g_Vt[base1 + t]     = __float2half_rn(acc[mi][ni][1] + b1);
                g_Vt[base0 + t + 8] = __float2half_rn(acc[mi][ni][2] + b0);
                g_Vt[base1 + t + 8] = __float2half_rn(acc[mi][ni][3] + b1);
            }
        }
    }
}

// ---------------- flash attention: fp16 MMA, split-KV -------------------------
#define BUF_U   4608            // u32 units per buffer
#define VS_OFF  2304
#define SMEM_B  (2 * BUF_U * 4) // 36864 bytes

__global__ __launch_bounds__(128, 4) void attn_kernel() {
    extern __shared__ unsigned smu[];
    __shared__ int keep_s[64];

    const int tid = threadIdx.x, lane = tid & 31, warp = tid >> 5;
    const int g = lane >> 2, tg = lane & 3;
    const int b = blockIdx.y;
    const int j = 31 - (blockIdx.x >> 2);      // heavy q-tiles first
    const int s = blockIdx.x & 3;
    const int q0 = j * 64;
    const int rb = warp * 16;
    const int unit = (b * 32 + j) * SPLITS + s;

    if (tid < 64) keep_s[tid] = g_keep[q0 + tid];
    __syncthreads();
    const int nkt = keep_s[63] / 64 + 1;
    const int csz = (nkt + SPLITS - 1) / SPLITS;
    const int kt0 = s * csz;
    const int kt1 = min(nkt, kt0 + csz);
    const int kq0 = keep_s[rb + g], kq1 = keep_s[rb + g + 8];

    if (kt0 >= kt1) {
        if ((lane & 3) == 0) {
            g_ml[(size_t)unit * 128 + rb + g]          = -1e30f;
            g_ml[(size_t)unit * 128 + rb + g + 8]      = -1e30f;
            g_ml[(size_t)unit * 128 + 64 + rb + g]     = 0.f;
            g_ml[(size_t)unit * 128 + 64 + rb + g + 8] = 0.f;
        }
        return;
    }

    unsigned smem_b;
    asm("{ .reg .u64 t; cvta.to.shared.u64 t, %1; cvt.u32.u64 %0, t; }"
        : "=r"(smem_b) : "l"(smu));

    // ---- stage Q (gathered rows) via cp.async into buffer 0 region
#pragma unroll
    for (int i = 0; i < 4; i++) {
        int gid = tid + i * 128;
        int r = gid >> 3, gc = gid & 7;
        cpa16(smem_b + (r * 36 + gc * 4) * 4,
              g_Qh + ((size_t)b * TT + keep_s[r]) * HSX + gc * 8);
    }
    asm volatile("cp.async.commit_group;");
    asm volatile("cp.async.wait_group 0;");
    __syncthreads();

    unsigned qf[4][4];
#pragma unroll
    for (int kc = 0; kc < 4; kc++) {
        qf[kc][0] = smu[(rb + g) * 36 + kc * 8 + tg];
        qf[kc][1] = smu[(rb + g + 8) * 36 + kc * 8 + tg];
        qf[kc][2] = smu[(rb + g) * 36 + kc * 8 + tg + 4];
        qf[kc][3] = smu[(rb + g + 8) * 36 + kc * 8 + tg + 4];
    }
    __syncthreads();   // Q region free for K/V buffers

    // ---- prologue: prefetch tile kt0 into buffer 0
    {
        const __half* Kb = g_Kh + ((size_t)b * TT + (size_t)kt0 * 64) * HSX;
        const __half* Vb = g_Vt + (size_t)b * HSX * TT + (size_t)kt0 * 64;
#pragma unroll
        for (int i = 0; i < 4; i++) {
            int gid = tid + i * 128;
            int r = gid >> 3, gc = gid & 7;
            cpa16(smem_b + (r * 36 + gc * 4) * 4,            Kb + (size_t)r * HSX + gc * 8);
            cpa16(smem_b + ((VS_OFF + r * 36 + gc * 4)) * 4, Vb + (size_t)r * TT + gc * 8);
        }
        asm volatile("cp.async.commit_group;");
    }

    float of[8][4];
#pragma unroll
    for (int i = 0; i < 8; i++)
#pragma unroll
        for (int jj = 0; jj < 4; jj++) of[i][jj] = 0.f;
    float m0_ = -1e30f, m1_ = -1e30f, l0 = 0.f, l1 = 0.f;

    for (int kt = kt0; kt < kt1; kt++) {
        if (kt + 1 < kt1) {
            const unsigned bo = ((kt + 1 - kt0) & 1) * BUF_U;
            const __half* Kb = g_Kh + ((size_t)b * TT + (size_t)(kt + 1) * 64) * HSX;
            const __half* Vb = g_Vt + (size_t)b * HSX * TT + (size_t)(kt + 1) * 64;
#pragma unroll
            for (int i = 0; i < 4; i++) {
                int gid = tid + i * 128;
                int r = gid >> 3, gc = gid & 7;
                cpa16(smem_b + (bo + r * 36 + gc * 4) * 4,          Kb + (size_t)r * HSX + gc * 8);
                cpa16(smem_b + (bo + VS_OFF + r * 36 + gc * 4) * 4, Vb + (size_t)r * TT + gc * 8);
            }
            asm volatile("cp.async.commit_group;");
            asm volatile("cp.async.wait_group 1;");
        } else {
            asm volatile("cp.async.wait_group 0;");
        }
        __syncthreads();

        const unsigned* Ks = smu + ((kt - kt0) & 1) * BUF_U;
        const unsigned* Vs = Ks + VS_OFF;

        // ---- S = Q @ K^T (16 rows x 64 keys)
        float sacc[8][4];
#pragma unroll
        for (int i = 0; i < 8; i++)
#pragma unroll
            for (int jj = 0; jj < 4; jj++) sacc[i][jj] = 0.f;
#pragma unroll
        for (int kc = 0; kc < 4; kc++) {
#pragma unroll
            for (int ni = 0; ni < 8; ni++) {
                unsigned bf[2];
                int kr = (ni * 8 + g) * 36 + kc * 8;
                bf[0] = Ks[kr + tg];
                bf[1] = Ks[kr + tg + 4];
                mma_f16(sacc[ni], qf[kc], bf);
            }
        }

        // ---- mask + warp-local online softmax
        const int tcol = kt * 64 + 2 * tg;
        float rmax0 = -1e30f, rmax1 = -1e30f;
#pragma unroll
        for (int ni = 0; ni < 8; ni++) {
            int t = tcol + ni * 8;
            if (t > kq0)     sacc[ni][0] = -1e30f;
            if (t + 1 > kq0) sacc[ni][1] = -1e30f;
            if (t > kq1)     sacc[ni][2] = -1e30f;
            if (t + 1 > kq1) sacc[ni][3] = -1e30f;
            rmax0 = fmaxf(rmax0, fmaxf(sacc[ni][0], sacc[ni][1]));
            rmax1 = fmaxf(rmax1, fmaxf(sacc[ni][2], sacc[ni][3]));
        }
        rmax0 = fmaxf(rmax0, __shfl_xor_sync(0xffffffffu, rmax0, 1));
        rmax0 = fmaxf(rmax0, __shfl_xor_sync(0xffffffffu, rmax0, 2));
        rmax1 = fmaxf(rmax1, __shfl_xor_sync(0xffffffffu, rmax1, 1));
        rmax1 = fmaxf(rmax1, __shfl_xor_sync(0xffffffffu, rmax1, 2));
        const float mn0 = fmaxf(m0_, rmax0), mn1 = fmaxf(m1_, rmax1);
        const float mb0 = (mn0 == -1e30f) ? 0.f : mn0;
        const float mb1 = (mn1 == -1e30f) ? 0.f : mn1;
        const float al0 = __expf(m0_ - mb0), al1 = __expf(m1_ - mb1);
        m0_ = mn0; m1_ = mn1;

        float rs0 = 0.f, rs1 = 0.f;
        unsigned pA[8], pB[8];
#pragma unroll
        for (int ni = 0; ni < 8; ni++) {
            sacc[ni][0] = __expf(sacc[ni][0] - mb0);
            sacc[ni][1] = __expf(sacc[ni][1] - mb0);
            sacc[ni][2] = __expf(sacc[ni][2] - mb1);
            sacc[ni][3] = __expf(sacc[ni][3] - mb1);
            rs0 += sacc[ni][0] + sacc[ni][1];
            rs1 += sacc[ni][2] + sacc[ni][3];
            pA[ni] = h2(sacc[ni][0], sacc[ni][1]);
            pB[ni] = h2(sacc[ni][2], sacc[ni][3]);
        }
        rs0 += __shfl_xor_sync(0xffffffffu, rs0, 1);
        rs0 += __shfl_xor_sync(0xffffffffu, rs0, 2);
        rs1 += __shfl_xor_sync(0xffffffffu, rs1, 1);
        rs1 += __shfl_xor_sync(0xffffffffu, rs1, 2);
        l0 = l0 * al0 + rs0;
        l1 = l1 * al1 + rs1;
#pragma unroll
        for (int ni = 0; ni < 8; ni++) {
            of[ni][0] *= al0; of[ni][1] *= al0;
            of[ni][2] *= al1; of[ni][3] *= al1;
        }

        // ---- O += P @ V  (A fragments straight from registers)
#pragma unroll
        for (int kb = 0; kb < 4; kb++) {
            unsigned a[4];
            a[0] = pA[2 * kb];
            a[1] = pB[2 * kb];
            a[2] = pA[2 * kb + 1];
            a[3] = pB[2 * kb + 1];
#pragma unroll
            for (int no = 0; no < 8; no++) {
                unsigned bf[2];
                int vr = (no * 8 + g) * 36 + kb * 8;
                bf[0] = Vs[vr + tg];
                bf[1] = Vs[vr + tg + 4];
                mma_f16(of[no], a, bf);
            }
        }
        __syncthreads();
    }

    // ---- write partial O and m, l
    const size_t obase = (size_t)unit * 64;
#pragma unroll
    for (int no = 0; no < 8; no++) {
        int c = no * 8 + 2 * tg;
        *(float2*)(g_Op + (obase + rb + g) * 64 + c) =
            make_float2(of[no][0], of[no][1]);
        *(float2*)(g_Op + (obase + rb + 8 + g) * 64 + c) =
            make_float2(of[no][2], of[no][3]);
    }
    if ((lane & 3) == 0) {
        g_ml[(size_t)unit * 128 + rb + g]          = m0_;
        g_ml[(size_t)unit * 128 + rb + g + 8]      = m1_;
        g_ml[(size_t)unit * 128 + 64 + rb + g]     = l0;
        g_ml[(size_t)unit * 128 + 64 + rb + g + 8] = l1;
    }
}

// ---------------- combine: merge 4 KV-split partials --------------------------
__global__ __launch_bounds__(128) void combine_kernel(float* __restrict__ out) {
    const int b = blockIdx.y, j = blockIdx.x;
    const int tid = threadIdx.x;
    const int r = tid >> 1, h = (tid & 1) * 32;
    const size_t ub = (size_t)(b * 32 + j) * SPLITS;

    float m[SPLITS], l[SPLITS];
    float mstar = -1e30f;
#pragma unroll
    for (int s = 0; s < SPLITS; s++) {
        m[s] = g_ml[(ub + s) * 128 + r];
        l[s] = g_ml[(ub + s) * 128 + 64 + r];
        mstar = fmaxf(mstar, m[s]);
    }
    float c[SPLITS], L = 0.f;
#pragma unroll
    for (int s = 0; s < SPLITS; s++) {
        c[s] = __expf(m[s] - mstar);
        L += l[s] * c[s];
    }
    const float inv = 1.f / L;
#pragma unroll
    for (int s = 0; s < SPLITS; s++) c[s] *= inv;

    const size_t orow = ((size_t)b * NKP + j * 64 + r) * HSX + h;
#pragma unroll
    for (int d = 0; d < 32; d += 4) {
        float4 acc = make_float4(0.f, 0.f, 0.f, 0.f);
#pragma unroll
        for (int s = 0; s < SPLITS; s++) {
            float4 v = *(const float4*)(g_Op + ((ub + s) * 64 + r) * 64 + h + d);
            acc.x += c[s] * v.x; acc.y += c[s] * v.y;
            acc.z += c[s] * v.z; acc.w += c[s] * v.w;
        }
        *(float4*)(out + orow + d) = acc;
    }
}

// ---------------- launcher ------------------------------------------------------
extern "C" void kernel_launch(void* const* d_in, const int* in_sizes, int n_in,
                              void* d_out, int out_size) {
    const float* x  = (const float*)d_in[0];
    const float* Wq = (const float*)d_in[1];
    const float* bq = (const float*)d_in[2];
    const float* Wk = (const float*)d_in[3];
    const float* bk = (const float*)d_in[4];
    const float* Wv = (const float*)d_in[5];
    const float* bv = (const float*)d_in[6];
    float* out = (float*)d_out;

    keep_kernel<<<(NKP + 255) / 256, 256>>>();
    proj_kernel<<<(BB * TT) / 128, 256>>>(x, Wq, bq, Wk, bk, Wv, bv);

    cudaFuncSetAttribute(attn_kernel,
                         cudaFuncAttributeMaxDynamicSharedMemorySize, SMEM_B);
    dim3 grd(32 * SPLITS, BB);
    attn_kernel<<<grd, 128, SMEM_B>>>();

    dim3 gc(32, BB);
    combine_kernel<<<gc, 128>>>(out);
}

// round 7
// speedup vs baseline: 7.4023x; 1.0724x over previous
#include <cuda_runtime.h>
#include <cuda_fp16.h>
#include <math.h>

#define BB  8
#define TT  4096
#define CC  1024
#define HSX 64
#define NKP 2048
// 1/sqrt(C) * log2(e): softmax runs in exp2 domain
#define QSCALE 0.0450842201f
#define SPLITS 4

// ---------------- scratch ----------------------------------------------------
__device__ int    g_keep[NKP];
__device__ __half g_Kh[(size_t)BB * TT * HSX];          // K, row-major half
__device__ __half g_Vt[(size_t)BB * HSX * TT];          // V transposed [b][d][t]
__device__ __half g_Qh[(size_t)BB * TT * HSX];          // Q half (all rows, pre-scaled)
__device__ float  g_Op[(size_t)BB * 32 * SPLITS * 64 * 64];
__device__ float  g_ml[(size_t)BB * 32 * SPLITS * 2 * 64];

// ---------------- helpers -----------------------------------------------------
__device__ __forceinline__ unsigned h2(float lo, float hi) {
    unsigned r;
    asm("cvt.rn.f16x2.f32 %0, %1, %2;" : "=r"(r) : "f"(hi), "f"(lo));
    return r;
}
__device__ __forceinline__ float ex2(float x) {
    float r; asm("ex2.approx.f32 %0, %1;" : "=f"(r) : "f"(x)); return r;
}
__device__ __forceinline__ void mma_f16(float d[4], const unsigned a[4],
                                        const unsigned b0, const unsigned b1) {
    asm("mma.sync.aligned.m16n8k16.row.col.f32.f16.f16.f32 "
        "{%0,%1,%2,%3}, {%4,%5,%6,%7}, {%8,%9}, {%0,%1,%2,%3};"
        : "+f"(d[0]), "+f"(d[1]), "+f"(d[2]), "+f"(d[3])
        : "r"(a[0]), "r"(a[1]), "r"(a[2]), "r"(a[3]), "r"(b0), "r"(b1));
}
__device__ __forceinline__ void ldsm4(unsigned& r0, unsigned& r1,
                                      unsigned& r2, unsigned& r3, unsigned a) {
    asm volatile("ldmatrix.sync.aligned.m8n8.x4.shared.b16 {%0,%1,%2,%3}, [%4];"
                 : "=r"(r0), "=r"(r1), "=r"(r2), "=r"(r3) : "r"(a));
}
__device__ __forceinline__ void cpa16(unsigned dst_smem, const void* src) {
    asm volatile("cp.async.ca.shared.global [%0], [%1], 16;"
                 :: "r"(dst_smem), "l"(src));
}
__device__ __forceinline__ unsigned s2u(const void* p) {
    unsigned r;
    asm("{ .reg .u64 t; cvta.to.shared.u64 t, %1; cvt.u32.u64 %0, t; }"
        : "=r"(r) : "l"(p));
    return r;
}

// ---------------- keep indices ------------------------------------------------
__global__ void keep_kernel() {
    int i = blockIdx.x * blockDim.x + threadIdx.x;
    if (i >= NKP) return;
    const int a = (TT + 3) / 4;
    int x = NKP - 1 - i;
    int v;
    if (x < a) v = TT - 1 - x;
    else {
        int k = x - a;
        double t = (3.0 / (double)a) * (double)k * (double)k + (double)a;
        v = TT - 1 - (int)ceil(t);
    }
    g_keep[i] = v;
}

// ---------------- fused Q,K,V projection: X[128,1024] @ W^T[1024,192] --------
__global__ __launch_bounds__(256) void proj_kernel(
    const float* __restrict__ x,
    const float* __restrict__ Wq, const float* __restrict__ bq,
    const float* __restrict__ Wk, const float* __restrict__ bk,
    const float* __restrict__ Wv, const float* __restrict__ bv)
{
    __shared__ unsigned Xs[128][20];   // 128 x 40 half
    __shared__ unsigned Ws[192][20];   // 192 x 40 half
    const int tid = threadIdx.x, lane = tid & 31, warp = tid >> 5;
    const int g = lane >> 2, tg = lane & 3;
    const int wm = warp >> 2, wn = warp & 3;      // 2 x 4 warps, tile 64 x 48
    const size_t m0 = (size_t)blockIdx.x * 128;
    const int bidx = blockIdx.x >> 5;
    const int t_in = (int)(m0 % TT);

    const unsigned wsb = s2u(Ws);
    const int lrow_m = (lane & 7) + ((lane >> 4) << 3);
    const int lcol_m = ((lane >> 3) & 1) * 4;

    float acc[4][6][4];
#pragma unroll
    for (int i = 0; i < 4; i++)
#pragma unroll
        for (int j = 0; j < 6; j++)
#pragma unroll
            for (int q = 0; q < 4; q++) acc[i][j][q] = 0.f;

    const int xr = tid >> 3, xc4 = (tid & 7) * 4, xcu = (tid & 7) * 2;

    float4 xv[4], wv[6];
#pragma unroll
    for (int s = 0; s < 4; s++)
        xv[s] = *(const float4*)(x + (m0 + xr + s * 32) * CC + xc4);
#pragma unroll
    for (int s = 0; s < 6; s++) {
        int idx = tid + s * 256;
        int r = idx >> 3, c4 = (idx & 7) * 4;
        const float* W = (r < 64) ? (Wq + (size_t)r * CC)
                       : (r < 128) ? (Wk + (size_t)(r - 64) * CC)
                                   : (Wv + (size_t)(r - 128) * CC);
        wv[s] = *(const float4*)(W + c4);
    }

    for (int k0 = 0; k0 < CC; k0 += 32) {
        __syncthreads();
#pragma unroll
        for (int s = 0; s < 4; s++) {
            int r = xr + s * 32;
            Xs[r][xcu]     = h2(xv[s].x, xv[s].y);
            Xs[r][xcu + 1] = h2(xv[s].z, xv[s].w);
        }
#pragma unroll
        for (int s = 0; s < 6; s++) {
            int idx = tid + s * 256;
            int r = idx >> 3, cu = (idx & 7) * 2;
            Ws[r][cu]     = h2(wv[s].x, wv[s].y);
            Ws[r][cu + 1] = h2(wv[s].z, wv[s].w);
        }
        __syncthreads();
        if (k0 + 32 < CC) {
            int k1 = k0 + 32;
#pragma unroll
            for (int s = 0; s < 4; s++)
                xv[s] = *(const float4*)(x + (m0 + xr + s * 32) * CC + k1 + xc4);
#pragma unroll
            for (int s = 0; s < 6; s++) {
                int idx = tid + s * 256;
                int r = idx >> 3, c4 = (idx & 7) * 4;
                const float* W = (r < 64) ? (Wq + (size_t)r * CC)
                               : (r < 128) ? (Wk + (size_t)(r - 64) * CC)
                                           : (Wv + (size_t)(r - 128) * CC);
                wv[s] = *(const float4*)(W + k1 + c4);
            }
        }
#pragma unroll
        for (int kc = 0; kc < 2; kc++) {
            const int kk = kc * 8;
            unsigned a[4][4], bf[6][2];
#pragma unroll
            for (int mi = 0; mi < 4; mi++) {
                int r = wm * 64 + mi * 16 + g;
                a[mi][0] = Xs[r][kk + tg];
                a[mi][1] = Xs[r + 8][kk + tg];
                a[mi][2] = Xs[r][kk + tg + 4];
                a[mi][3] = Xs[r + 8][kk + tg + 4];
            }
#pragma unroll
            for (int p = 0; p < 3; p++) {
                unsigned ad = wsb +
                    (((wn * 48 + p * 16 + lrow_m) * 20) + kk + lcol_m) * 4;
                ldsm4(bf[2 * p][0], bf[2 * p][1],
                      bf[2 * p + 1][0], bf[2 * p + 1][1], ad);
            }
#pragma unroll
            for (int mi = 0; mi < 4; mi++)
#pragma unroll
                for (int ni = 0; ni < 6; ni++)
                    mma_f16(acc[mi][ni], a[mi], bf[ni][0], bf[ni][1]);
        }
    }

#pragma unroll
    for (int mi = 0; mi < 4; mi++) {
        size_t row = m0 + wm * 64 + mi * 16 + g;
        int t = t_in + wm * 64 + mi * 16 + g;
#pragma unroll
        for (int ni = 0; ni < 6; ni++) {
            int col = wn * 48 + ni * 8 + 2 * tg;
            if (col < 64) {                         // Q (scaled, exp2 domain)
                float b0 = bq[col], b1 = bq[col + 1];
                ((unsigned*)g_Qh)[row * 32 + col / 2] =
                    h2((acc[mi][ni][0] + b0) * QSCALE, (acc[mi][ni][1] + b1) * QSCALE);
                ((unsigned*)g_Qh)[(row + 8) * 32 + col / 2] =
                    h2((acc[mi][ni][2] + b0) * QSCALE, (acc[mi][ni][3] + b1) * QSCALE);
            } else if (col < 128) {                 // K
                int c = col - 64;
                float b0 = bk[c], b1 = bk[c + 1];
                ((unsigned*)g_Kh)[row * 32 + c / 2] =
                    h2(acc[mi][ni][0] + b0, acc[mi][ni][1] + b1);
                ((unsigned*)g_Kh)[(row + 8) * 32 + c / 2] =
                    h2(acc[mi][ni][2] + b0, acc[mi][ni][3] + b1);
            } else {                                // V (transposed store)
                int c = col - 128;
                float b0 = bv[c], b1 = bv[c + 1];
                size_t base0 = ((size_t)bidx * HSX + c) * TT;
                size_t base1 = base0 + TT;
                g_Vt[base0 + t]     = __float2half_rn(acc[mi][ni][0] + b0);
                g_Vt[base1 + t]     = __float2half_rn(acc[mi][ni][1] + b1);
                g_Vt[base0 + t + 8] = __float2half_rn(acc[mi][ni][2] + b0);
                g_Vt[base1 + t + 8] = __float2half_rn(acc[mi][ni][3] + b1);
            }
        }
    }
}

// ---------------- flash attention: fp16 MMA + ldmatrix, split-KV -------------
#define BUF_U   4608            // u32 units per buffer
#define VS_OFF  2304
#define SMEM_B  (2 * BUF_U * 4) // 36864 bytes

__global__ __launch_bounds__(128, 4) void attn_kernel() {
    extern __shared__ unsigned smu[];
    __shared__ int keep_s[64];

    const int tid = threadIdx.x, lane = tid & 31, warp = tid >> 5;
    const int g = lane >> 2, tg = lane & 3;
    const int b = blockIdx.y;
    const int j = 31 - (blockIdx.x >> 2);
    const int s = blockIdx.x & 3;
    const int q0 = j * 64;
    const int rb = warp * 16;
    const int unit = (b * 32 + j) * SPLITS + s;

    if (tid < 64) keep_s[tid] = g_keep[q0 + tid];
    __syncthreads();
    const int nkt = keep_s[63] / 64 + 1;
    const int csz = (nkt + SPLITS - 1) / SPLITS;
    const int kt0 = s * csz;
    const int kt1 = min(nkt, kt0 + csz);
    const int kq0 = keep_s[rb + g], kq1 = keep_s[rb + g + 8];

    if (kt0 >= kt1) {
        if ((lane & 3) == 0) {
            g_ml[(size_t)unit * 128 + rb + g]          = -1e30f;
            g_ml[(size_t)unit * 128 + rb + g + 8]      = -1e30f;
            g_ml[(size_t)unit * 128 + 64 + rb + g]     = 0.f;
            g_ml[(size_t)unit * 128 + 64 + rb + g + 8] = 0.f;
        }
        return;
    }

    const unsigned smem_b = s2u(smu);
    // per-lane ldmatrix offset within a [rows][36 u32] tile (bytes)
    const unsigned moff = (((lane & 7) + ((lane >> 4) << 3)) * 36 +
                           ((lane >> 3) & 1) * 4) * 4;

    // ---- stage Q (gathered rows) into buffer 0 region
#pragma unroll
    for (int i = 0; i < 4; i++) {
        int gid = tid + i * 128;
        int r = gid >> 3, gc = gid & 7;
        cpa16(smem_b + (r * 36 + gc * 4) * 4,
              g_Qh + ((size_t)b * TT + keep_s[r]) * HSX + gc * 8);
    }
    asm volatile("cp.async.commit_group;");
    asm volatile("cp.async.wait_group 0;");
    __syncthreads();

    unsigned qf[4][4];
#pragma unroll
    for (int kc = 0; kc < 4; kc++) {
        qf[kc][0] = smu[(rb + g) * 36 + kc * 8 + tg];
        qf[kc][1] = smu[(rb + g + 8) * 36 + kc * 8 + tg];
        qf[kc][2] = smu[(rb + g) * 36 + kc * 8 + tg + 4];
        qf[kc][3] = smu[(rb + g + 8) * 36 + kc * 8 + tg + 4];
    }
    __syncthreads();

    // ---- prologue: prefetch tile kt0 into buffer 0
    {
        const __half* Kb = g_Kh + ((size_t)b * TT + (size_t)kt0 * 64) * HSX;
        const __half* Vb = g_Vt + (size_t)b * HSX * TT + (size_t)kt0 * 64;
#pragma unroll
        for (int i = 0; i < 4; i++) {
            int gid = tid + i * 128;
            int r = gid >> 3, gc = gid & 7;
            cpa16(smem_b + (r * 36 + gc * 4) * 4,            Kb + (size_t)r * HSX + gc * 8);
            cpa16(smem_b + ((VS_OFF + r * 36 + gc * 4)) * 4, Vb + (size_t)r * TT + gc * 8);
        }
        asm volatile("cp.async.commit_group;");
    }

    float of[8][4];
#pragma unroll
    for (int i = 0; i < 8; i++)
#pragma unroll
        for (int jj = 0; jj < 4; jj++) of[i][jj] = 0.f;
    float m0_ = -1e30f, m1_ = -1e30f, l0 = 0.f, l1 = 0.f;

    for (int kt = kt0; kt < kt1; kt++) {
        if (kt + 1 < kt1) {
            const unsigned bo = ((kt + 1 - kt0) & 1) * BUF_U;
            const __half* Kb = g_Kh + ((size_t)b * TT + (size_t)(kt + 1) * 64) * HSX;
            const __half* Vb = g_Vt + (size_t)b * HSX * TT + (size_t)(kt + 1) * 64;
#pragma unroll
            for (int i = 0; i < 4; i++) {
                int gid = tid + i * 128;
                int r = gid >> 3, gc = gid & 7;
                cpa16(smem_b + (bo + r * 36 + gc * 4) * 4,          Kb + (size_t)r * HSX + gc * 8);
                cpa16(smem_b + (bo + VS_OFF + r * 36 + gc * 4) * 4, Vb + (size_t)r * TT + gc * 8);
            }
            asm volatile("cp.async.commit_group;");
            asm volatile("cp.async.wait_group 1;");
        } else {
            asm volatile("cp.async.wait_group 0;");
        }
        __syncthreads();

        const unsigned ks_b = smem_b + (((kt - kt0) & 1) * BUF_U) * 4;
        const unsigned vs_b = ks_b + VS_OFF * 4;

        // ---- S = Q @ K^T (16 rows x 64 keys), B-frags via ldmatrix
        float sacc[8][4];
#pragma unroll
        for (int i = 0; i < 8; i++)
#pragma unroll
            for (int jj = 0; jj < 4; jj++) sacc[i][jj] = 0.f;
#pragma unroll
        for (int kc = 0; kc < 4; kc++) {
#pragma unroll
            for (int nb = 0; nb < 4; nb++) {
                unsigned b0, b1, b2, b3;
                ldsm4(b0, b1, b2, b3,
                      ks_b + (unsigned)(nb * 16 * 36 + kc * 8) * 4 + moff);
                mma_f16(sacc[2 * nb],     qf[kc], b0, b1);
                mma_f16(sacc[2 * nb + 1], qf[kc], b2, b3);
            }
        }

        // ---- mask + warp-local online softmax (exp2 domain)
        const int tcol = kt * 64 + 2 * tg;
        float rmax0 = -1e30f, rmax1 = -1e30f;
#pragma unroll
        for (int ni = 0; ni < 8; ni++) {
            int t = tcol + ni * 8;
            if (t > kq0)     sacc[ni][0] = -1e30f;
            if (t + 1 > kq0) sacc[ni][1] = -1e30f;
            if (t > kq1)     sacc[ni][2] = -1e30f;
            if (t + 1 > kq1) sacc[ni][3] = -1e30f;
            rmax0 = fmaxf(rmax0, fmaxf(sacc[ni][0], sacc[ni][1]));
            rmax1 = fmaxf(rmax1, fmaxf(sacc[ni][2], sacc[ni][3]));
        }
        rmax0 = fmaxf(rmax0, __shfl_xor_sync(0xffffffffu, rmax0, 1));
        rmax0 = fmaxf(rmax0, __shfl_xor_sync(0xffffffffu, rmax0, 2));
        rmax1 = fmaxf(rmax1, __shfl_xor_sync(0xffffffffu, rmax1, 1));
        rmax1 = fmaxf(rmax1, __shfl_xor_sync(0xffffffffu, rmax1, 2));
        const float mn0 = fmaxf(m0_, rmax0), mn1 = fmaxf(m1_, rmax1);
        const float mb0 = (mn0 == -1e30f) ? 0.f : mn0;
        const float mb1 = (mn1 == -1e30f) ? 0.f : mn1;
        const float al0 = ex2(m0_ - mb0), al1 = ex2(m1_ - mb1);
        m0_ = mn0; m1_ = mn1;

        float rs0 = 0.f, rs1 = 0.f;
        unsigned pA[8], pB[8];
#pragma unroll
        for (int ni = 0; ni < 8; ni++) {
            sacc[ni][0] = ex2(sacc[ni][0] - mb0);
            sacc[ni][1] = ex2(sacc[ni][1] - mb0);
            sacc[ni][2] = ex2(sacc[ni][2] - mb1);
            sacc[ni][3] = ex2(sacc[ni][3] - mb1);
            rs0 += sacc[ni][0] + sacc[ni][1];
            rs1 += sacc[ni][2] + sacc[ni][3];
            pA[ni] = h2(sacc[ni][0], sacc[ni][1]);
            pB[ni] = h2(sacc[ni][2], sacc[ni][3]);
        }
        rs0 += __shfl_xor_sync(0xffffffffu, rs0, 1);
        rs0 += __shfl_xor_sync(0xffffffffu, rs0, 2);
        rs1 += __shfl_xor_sync(0xffffffffu, rs1, 1);
        rs1 += __shfl_xor_sync(0xffffffffu, rs1, 2);
        l0 = l0 * al0 + rs0;
        l1 = l1 * al1 + rs1;
#pragma unroll
        for (int ni = 0; ni < 8; ni++) {
            of[ni][0] *= al0; of[ni][1] *= al0;
            of[ni][2] *= al1; of[ni][3] *= al1;
        }

        // ---- O += P @ V (A from regs, B via ldmatrix)
#pragma unroll
        for (int kb = 0; kb < 4; kb++) {
            unsigned a[4];
            a[0] = pA[2 * kb];
            a[1] = pB[2 * kb];
            a[2] = pA[2 * kb + 1];
            a[3] = pB[2 * kb + 1];
#pragma unroll
            for (int nb = 0; nb < 4; nb++) {
                unsigned b0, b1, b2, b3;
                ldsm4(b0, b1, b2, b3,
                      vs_b + (unsigned)(nb * 16 * 36 + kb * 8) * 4 + moff);
                mma_f16(of[2 * nb],     a, b0, b1);
                mma_f16(of[2 * nb + 1], a, b2, b3);
            }
        }
        __syncthreads();
    }

    // ---- write partial O and m, l
    const size_t obase = (size_t)unit * 64;
#pragma unroll
    for (int no = 0; no < 8; no++) {
        int c = no * 8 + 2 * tg;
        *(float2*)(g_Op + (obase + rb + g) * 64 + c) =
            make_float2(of[no][0], of[no][1]);
        *(float2*)(g_Op + (obase + rb + 8 + g) * 64 + c) =
            make_float2(of[no][2], of[no][3]);
    }
    if ((lane & 3) == 0) {
        g_ml[(size_t)unit * 128 + rb + g]          = m0_;
        g_ml[(size_t)unit * 128 + rb + g + 8]      = m1_;
        g_ml[(size_t)unit * 128 + 64 + rb + g]     = l0;
        g_ml[(size_t)unit * 128 + 64 + rb + g + 8] = l1;
    }
}

// ---------------- combine: merge 4 KV-split partials (512 thr) ---------------
__global__ __launch_bounds__(512) void combine_kernel(float* __restrict__ out) {
    const int b = blockIdx.y, j = blockIdx.x;
    const int tid = threadIdx.x;
    const int r = tid >> 3, seg = (tid & 7) * 8;
    const size_t ub = (size_t)(b * 32 + j) * SPLITS;

    float m[SPLITS], l[SPLITS];
    float mstar = -1e30f;
#pragma unroll
    for (int s = 0; s < SPLITS; s++) {
        m[s] = g_ml[(ub + s) * 128 + r];
        l[s] = g_ml[(ub + s) * 128 + 64 + r];
        mstar = fmaxf(mstar, m[s]);
    }
    float c[SPLITS], L = 0.f;
#pragma unroll
    for (int s = 0; s < SPLITS; s++) {
        c[s] = ex2(m[s] - mstar);
        L += l[s] * c[s];
    }
    const float inv = 1.f / L;
#pragma unroll
    for (int s = 0; s < SPLITS; s++) c[s] *= inv;

    float4 a0 = make_float4(0.f, 0.f, 0.f, 0.f);
    float4 a1 = make_float4(0.f, 0.f, 0.f, 0.f);
#pragma unroll
    for (int s = 0; s < SPLITS; s++) {
        const float* src = g_Op + ((ub + s) * 64 + r) * 64 + seg;
        float4 v0 = *(const float4*)(src);
        float4 v1 = *(const float4*)(src + 4);
        a0.x += c[s] * v0.x; a0.y += c[s] * v0.y;
        a0.z += c[s] * v0.z; a0.w += c[s] * v0.w;
        a1.x += c[s] * v1.x; a1.y += c[s] * v1.y;
        a1.z += c[s] * v1.z; a1.w += c[s] * v1.w;
    }
    const size_t orow = ((size_t)b * NKP + j * 64 + r) * HSX + seg;
    *(float4*)(out + orow)     = a0;
    *(float4*)(out + orow + 4) = a1;
}

// ---------------- launcher ------------------------------------------------------
extern "C" void kernel_launch(void* const* d_in, const int* in_sizes, int n_in,
                              void* d_out, int out_size) {
    const float* x  = (const float*)d_in[0];
    const float* Wq = (const float*)d_in[1];
    const float* bq = (const float*)d_in[2];
    const float* Wk = (const float*)d_in[3];
    const float* bk = (const float*)d_in[4];
    const float* Wv = (const float*)d_in[5];
    const float* bv = (const float*)d_in[6];
    float* out = (float*)d_out;

    keep_kernel<<<(NKP + 255) / 256, 256>>>();
    proj_kernel<<<(BB * TT) / 128, 256>>>(x, Wq, bq, Wk, bk, Wv, bv);

    cudaFuncSetAttribute(attn_kernel,
                         cudaFuncAttributeMaxDynamicSharedMemorySize, SMEM_B);
    dim3 grd(32 * SPLITS, BB);
    attn_kernel<<<grd, 128, SMEM_B>>>();

    dim3 gc(32, BB);
    combine_kernel<<<gc, 512>>>(out);
}